// round 8
// baseline (speedup 1.0000x reference)
#include <cuda_runtime.h>
#include <cuda_fp16.h>
#include <math.h>
#include <stdint.h>

#define T_SEQ 20
#define NF    812
#define HID   400
#define NG    1600            // 4*HID
#define BATCH 8192
#define MROWS (BATCH * T_SEQ) // 163840
#define KP    832             // per-section K big GEMM (26*32)
#define K2    (2 * KP)        // V2 row stride: [hi | lo]
#define KHS   416             // gates per-section K (13*32)
#define KH2   (2 * KHS)       // h2 row stride: [hi | lo]
#define NCBIG (KP / 32)       // 26 dual-section chunks
#define NCGAT (KHS / 32)      // 13
#define NBN   (NG / 64)       // 25 n-tiles

// ---------------- device scratch ----------------
__device__ __half g_V2[(size_t)MROWS * K2];          // ~545 MB [hi|lo] split values
__device__ __half g_W2[(size_t)NG * KP];             // ~2.7 MB W_ih fp16 (perm rows, single copy)
__device__ __half g_Wh2[(size_t)NG * KHS];           // ~1.3 MB W_hh fp16 (perm rows)
__device__ __half g_h2[2][(size_t)BATCH * KH2];      // [hi|lo] decayed h (dbl buf)
__device__ float g_G0[(size_t)MROWS * NG];           // ~1.05 GB perm gate pre-acts
__device__ float g_c [BATCH * HID];
__device__ float g_xh_part[2][NBN][BATCH];           // per-bn regression partials (dbl buf)
__device__ float g_wsum[HID];
__device__ float g_num[T_SEQ];
__device__ float g_den[T_SEQ];

// ---------------- PTX helpers ----------------
__device__ __forceinline__ uint32_t smem_u32(const void* p) {
    uint32_t a;
    asm("{ .reg .u64 t; cvta.to.shared.u64 t, %1; cvt.u32.u64 %0, t; }" : "=r"(a) : "l"(p));
    return a;
}
__device__ __forceinline__ void cp_async16(uint32_t saddr, const void* gaddr) {
    asm volatile("cp.async.cg.shared.global [%0], [%1], 16;\n" :: "r"(saddr), "l"(gaddr) : "memory");
}
__device__ __forceinline__ void ldsm_x4(uint32_t* r, uint32_t addr) {
    asm volatile("ldmatrix.sync.aligned.m8n8.x4.shared.b16 {%0,%1,%2,%3}, [%4];"
                 : "=r"(r[0]), "=r"(r[1]), "=r"(r[2]), "=r"(r[3]) : "r"(addr));
}
__device__ __forceinline__ void mma16816(float* d, const uint32_t* a, const uint32_t* b) {
    asm volatile(
        "mma.sync.aligned.m16n8k16.row.col.f32.f16.f16.f32 "
        "{%0,%1,%2,%3}, {%4,%5,%6,%7}, {%8,%9}, {%0,%1,%2,%3};"
        : "+f"(d[0]), "+f"(d[1]), "+f"(d[2]), "+f"(d[3])
        : "r"(a[0]), "r"(a[1]), "r"(a[2]), "r"(a[3]), "r"(b[0]), "r"(b[1]));
}

// smem stage: A_hi 128x32 (80B stride) | A_lo 128x32 | B 64x32
#define A_STRIDE_B 80
#define A_TILE_B   (128 * A_STRIDE_B)    // 10240
#define B_TILE_B   (64 * A_STRIDE_B)     // 5120
#define ALO_OFF    A_TILE_B              // 10240
#define B_OFF      (2 * A_TILE_B)        // 20480
#define BUF_B      (2 * A_TILE_B + B_TILE_B) // 25600 per stage
#define NSTAGE     3
#define SMEM_DYN   (NSTAGE * BUF_B)      // 76800; epilogue stage 33792 fits

// ------ mma mainloop: dual-A-section vs shared B (BM=128, BN=64, BK=32, 8 warps) ------
__device__ __forceinline__ void gemm_mainloop(
    const __half* Abase, const __half* Bbase,
    int aStride, int aSect, int bStride, int nChunks,
    uint32_t sbuf, float acc[2][4][4], int tid)
{
    int lane = tid & 31, w = tid >> 5;
    int wm = w & 3, wn = w >> 2;
    uint32_t aOffBase = (uint32_t)((wm * 32 + (lane & 15)) * A_STRIDE_B + ((lane >> 4) << 4));
    uint32_t bOffBase = (uint32_t)(B_OFF +
        (wn * 32 + ((lane >> 4) << 3) + (lane & 7)) * A_STRIDE_B + (((lane >> 3) & 1) << 4));

    int lrow = tid >> 2, lseg = tid & 3;

    // preload chunks 0, 1
    #pragma unroll
    for (int pc = 0; pc < 2; pc++) {
        uint32_t dst = sbuf + pc * BUF_B;
        int koff = pc * 32;
        cp_async16(dst + lrow * A_STRIDE_B + lseg * 16,
                   Abase + (size_t)lrow * aStride + koff + lseg * 8);
        cp_async16(dst + (lrow + 64) * A_STRIDE_B + lseg * 16,
                   Abase + (size_t)(lrow + 64) * aStride + koff + lseg * 8);
        cp_async16(dst + ALO_OFF + lrow * A_STRIDE_B + lseg * 16,
                   Abase + (size_t)lrow * aStride + aSect + koff + lseg * 8);
        cp_async16(dst + ALO_OFF + (lrow + 64) * A_STRIDE_B + lseg * 16,
                   Abase + (size_t)(lrow + 64) * aStride + aSect + koff + lseg * 8);
        cp_async16(dst + B_OFF + lrow * A_STRIDE_B + lseg * 16,
                   Bbase + (size_t)lrow * bStride + koff + lseg * 8);
        asm volatile("cp.async.commit_group;\n" ::: "memory");
    }

    int bufc = 0, bufn = 2;
    for (int c = 0; c < nChunks; c++) {
        if (c + 1 < nChunks) {
            asm volatile("cp.async.wait_group 1;\n" ::: "memory");
        } else {
            asm volatile("cp.async.wait_group 0;\n" ::: "memory");
        }
        __syncthreads();

        if (c + 2 < nChunks) {
            uint32_t dst = sbuf + bufn * BUF_B;
            int koff = (c + 2) * 32;
            cp_async16(dst + lrow * A_STRIDE_B + lseg * 16,
                       Abase + (size_t)lrow * aStride + koff + lseg * 8);
            cp_async16(dst + (lrow + 64) * A_STRIDE_B + lseg * 16,
                       Abase + (size_t)(lrow + 64) * aStride + koff + lseg * 8);
            cp_async16(dst + ALO_OFF + lrow * A_STRIDE_B + lseg * 16,
                       Abase + (size_t)lrow * aStride + aSect + koff + lseg * 8);
            cp_async16(dst + ALO_OFF + (lrow + 64) * A_STRIDE_B + lseg * 16,
                       Abase + (size_t)(lrow + 64) * aStride + aSect + koff + lseg * 8);
            cp_async16(dst + B_OFF + lrow * A_STRIDE_B + lseg * 16,
                       Bbase + (size_t)lrow * bStride + koff + lseg * 8);
            asm volatile("cp.async.commit_group;\n" ::: "memory");
        }

        uint32_t cur = sbuf + bufc * BUF_B;
        #pragma unroll
        for (int kc = 0; kc < 2; kc++) {
            uint32_t ahi[2][4], alo[2][4], bregs[2][4];
            ldsm_x4(ahi[0], cur + aOffBase + kc * 32);
            ldsm_x4(ahi[1], cur + aOffBase + 16 * A_STRIDE_B + kc * 32);
            ldsm_x4(alo[0], cur + ALO_OFF + aOffBase + kc * 32);
            ldsm_x4(alo[1], cur + ALO_OFF + aOffBase + 16 * A_STRIDE_B + kc * 32);
            ldsm_x4(bregs[0], cur + bOffBase + kc * 32);
            ldsm_x4(bregs[1], cur + bOffBase + 16 * A_STRIDE_B + kc * 32);
            #pragma unroll
            for (int mi = 0; mi < 2; mi++)
                #pragma unroll
                for (int ni = 0; ni < 4; ni++) {
                    mma16816(acc[mi][ni], ahi[mi], &bregs[ni >> 1][(ni & 1) * 2]);
                    mma16816(acc[mi][ni], alo[mi], &bregs[ni >> 1][(ni & 1) * 2]);
                }
        }
        bufc = (bufc == 2) ? 0 : bufc + 1;
        bufn = (bufn == 2) ? 0 : bufn + 1;
    }
    __syncthreads();  // protect smem before epilogue staging reuses it
}

// stage acc -> smem fp32 [128][66]
__device__ __forceinline__ void stage_acc(float* stage, float acc[2][4][4], int tid) {
    int lane = tid & 31, w = tid >> 5;
    int wm = w & 3, wn = w >> 2;
    #pragma unroll
    for (int mi = 0; mi < 2; mi++)
        #pragma unroll
        for (int ni = 0; ni < 4; ni++) {
            int r0 = wm * 32 + mi * 16 + (lane >> 2);
            int cc = wn * 32 + ni * 8 + (lane & 3) * 2;
            *(float2*)&stage[r0 * 66 + cc]       = make_float2(acc[mi][ni][0], acc[mi][ni][1]);
            *(float2*)&stage[(r0 + 8) * 66 + cc] = make_float2(acc[mi][ni][2], acc[mi][ni][3]);
        }
}

// ---------------- init ----------------
__global__ void k_init() {
    long i = (long)blockIdx.x * blockDim.x + threadIdx.x;
    long stride = (long)gridDim.x * blockDim.x;
    for (long p = i; p < (long)BATCH * HID; p += stride) g_c[p] = 0.f;
    for (long p = i; p < 2L * BATCH * KH2; p += stride) ((__half*)g_h2)[p] = __float2half(0.f);
    for (long p = i; p < 2L * NBN * BATCH; p += stride) ((float*)g_xh_part)[p] = 0.f;
    if (i < T_SEQ) { g_num[i] = 0.f; g_den[i] = 0.f; }
}

// ---------------- w_sum ----------------
__global__ void k_wsum(const float* __restrict__ Wd) {
    int row = blockIdx.x;
    __shared__ float red[256];
    float s = 0.f;
    for (int k = threadIdx.x; k < NF; k += 256) s += Wd[(size_t)row * NF + k];
    red[threadIdx.x] = s;
    __syncthreads();
    for (int off = 128; off; off >>= 1) {
        if (threadIdx.x < off) red[threadIdx.x] += red[threadIdx.x + off];
        __syncthreads();
    }
    if (threadIdx.x == 0) g_wsum[row] = red[0];
}

// ---------------- V2 = [hi(V) | lo(V)] (exact split) ----------------
__global__ void k_convV(const float* __restrict__ V) {
    int r = blockIdx.x;
    const float* src = V + (size_t)r * NF;
    __half* dst = g_V2 + (size_t)r * K2;
    for (int k = threadIdx.x; k < KP; k += 256) {
        float v = (k < NF) ? src[k] : 0.f;
        __half hi = __float2half_rn(v);
        __half lo = __float2half_rn(v - __half2float(hi));
        dst[k] = hi; dst[KP + k] = lo;
    }
}

// ---------------- W2 rows permuted (n = j*4+g), single fp16 copy ----------------
__global__ void k_convW(const float* __restrict__ Wih) {
    int n = blockIdx.x;
    int orig = (n & 3) * HID + (n >> 2);
    __half* dst = g_W2 + (size_t)n * KP;
    const float* src = Wih + (size_t)orig * (NF + 1);
    for (int k = threadIdx.x; k < KP; k += 256)
        dst[k] = __float2half_rn((k < NF) ? src[k] : 0.f);
}

// ---------------- Wh2 rows permuted, single fp16 copy, pad to 416 ----------------
__global__ void k_convWh(const float* __restrict__ Whh) {
    int n = blockIdx.x;
    int orig = (n & 3) * HID + (n >> 2);
    __half* dst = g_Wh2 + (size_t)n * KHS;
    const float* src = Whh + (size_t)orig * HID;
    for (int k = threadIdx.x; k < KHS; k += 256)
        dst[k] = __float2half_rn((k < HID) ? src[k] : 0.f);
}

// ---------------- big GEMM: G0(perm) = V2 @ W2^T + bias ----------------
__global__ __launch_bounds__(256) void k_bigmma(const float* __restrict__ bih,
                                                const float* __restrict__ bhh)
{
    extern __shared__ char smem[];
    uint32_t sbuf = smem_u32(smem);
    float* stage = (float*)smem;
    __shared__ float biasS[64];
    int tid = threadIdx.x;
    int bn = blockIdx.x, bm = blockIdx.y;

    if (tid < 64) {
        int np = bn * 64 + tid;
        int orig = (np & 3) * HID + (np >> 2);
        biasS[tid] = bih[orig] + bhh[orig];
    }

    float acc[2][4][4];
    #pragma unroll
    for (int a = 0; a < 2; a++)
        #pragma unroll
        for (int b = 0; b < 4; b++)
            #pragma unroll
            for (int c = 0; c < 4; c++) acc[a][b][c] = 0.f;

    gemm_mainloop(g_V2 + (size_t)(bm * 128) * K2, g_W2 + (size_t)(bn * 64) * KP,
                  K2, KP, KP, NCBIG, sbuf, acc, tid);

    stage_acc(stage, acc, tid);
    __syncthreads();

    #pragma unroll
    for (int i = 0; i < 8; i++) {
        int lin = tid + i * 256;
        int r = lin >> 4, c4 = lin & 15;
        float4 v;
        v.x = stage[r * 66 + c4 * 4 + 0] + biasS[c4 * 4 + 0];
        v.y = stage[r * 66 + c4 * 4 + 1] + biasS[c4 * 4 + 1];
        v.z = stage[r * 66 + c4 * 4 + 2] + biasS[c4 * 4 + 2];
        v.w = stage[r * 66 + c4 * 4 + 3] + biasS[c4 * 4 + 3];
        *(float4*)&g_G0[(size_t)(bm * 128 + r) * NG + bn * 64 + c4 * 4] = v;
    }
}

// ---------------- recurrent GEMM + imputation prologue + fused LSTM cell ----------------
__global__ __launch_bounds__(256) void k_gates(
    const float* __restrict__ V, const float* __restrict__ Wih,
    const float* __restrict__ masks, const float* __restrict__ deltas,
    const float* __restrict__ bdec, const float* __restrict__ Wreg,
    const float* __restrict__ breg, float* __restrict__ outImp, int t)
{
    extern __shared__ char smem[];
    uint32_t sbuf = smem_u32(smem);
    float* stage = (float*)smem;
    __shared__ float wvS[64], wmS[64];
    __shared__ float wsumS[16], bdecS[16], wregS[16];
    __shared__ float alphaS[128], mS[128];
    __shared__ float lossRed[2];
    int tid = threadIdx.x;
    int bn = blockIdx.x, bm = blockIdx.y;
    int par = t & 1;

    if (tid < 64) {
        int np = bn * 64 + tid;
        int orig = (np & 3) * HID + (np >> 2);
        wvS[tid] = Wih[(size_t)orig * (NF + 1) + (NF - 1)];
        wmS[tid] = Wih[(size_t)orig * (NF + 1) + NF];
    }
    if (tid >= 64 && tid < 80) {
        int jl = tid - 64;
        int j = bn * 16 + jl;
        wsumS[jl] = g_wsum[j];
        bdecS[jl] = bdec[j];
        wregS[jl] = Wreg[j];
    }
    if (tid == 0) { lossRed[0] = 0.f; lossRed[1] = 0.f; }

    // ---- prologue: per-row regression xh, imputation, alpha, loss ----
    {
        float nloc = 0.f, dloc = 0.f;
        if (tid < 128) {
            int b = bm * 128 + tid;
            float xh = breg[0];
            #pragma unroll
            for (int p = 0; p < NBN; p++) xh += g_xh_part[par][p][b];
            float m  = masks[b * T_SEQ + t];
            float v  = V[((size_t)b * T_SEQ + t) * NF + (NF - 1)];
            float xvar = v * m + (1.f - m) * xh;
            alphaS[tid] = xvar - v;
            mS[tid] = m;
            if (bn == 0) {
                outImp[b * T_SEQ + t] = xvar;
                nloc = fabsf(xvar - xh) * m;
                dloc = m;
            }
        }
        if (bn == 0) {
            #pragma unroll
            for (int off = 16; off; off >>= 1) {
                nloc += __shfl_xor_sync(0xffffffff, nloc, off);
                dloc += __shfl_xor_sync(0xffffffff, dloc, off);
            }
            if (tid < 128 && (tid & 31) == 0) {
                atomicAdd(&lossRed[0], nloc);
                atomicAdd(&lossRed[1], dloc);
            }
        }
    }
    __syncthreads();
    if (bn == 0 && tid == 0) {
        atomicAdd(&g_num[t], lossRed[0]);
        atomicAdd(&g_den[t], lossRed[1]);
    }

    float acc[2][4][4];
    #pragma unroll
    for (int a = 0; a < 2; a++)
        #pragma unroll
        for (int b = 0; b < 4; b++)
            #pragma unroll
            for (int c = 0; c < 4; c++) acc[a][b][c] = 0.f;

    gemm_mainloop(g_h2[par] + (size_t)(bm * 128) * KH2, g_Wh2 + (size_t)(bn * 64) * KHS,
                  KH2, KHS, KHS, NCGAT, sbuf, acc, tid);

    stage_acc(stage, acc, tid);
    __syncthreads();

    __half* h2n = g_h2[1 - par];
    bool more = (t + 1 < T_SEQ);
    float xh_i[8];
    #pragma unroll
    for (int i = 0; i < 8; i++) xh_i[i] = 0.f;

    #pragma unroll
    for (int i = 0; i < 8; i++) {
        int lin = tid + i * 256;       // 128 rows x 16 jl
        int r = lin >> 4, jl = lin & 15;
        int b = bm * 128 + r;
        float alpha = alphaS[r];
        float m = mS[r];
        int c0 = jl * 4;
        float4 g0 = *(const float4*)&g_G0[((size_t)b * T_SEQ + t) * NG + bn * 64 + c0];
        float ig = stage[r * 66 + c0 + 0] + g0.x + alpha * wvS[c0 + 0] + m * wmS[c0 + 0];
        float fg = stage[r * 66 + c0 + 1] + g0.y + alpha * wvS[c0 + 1] + m * wmS[c0 + 1];
        float gg = stage[r * 66 + c0 + 2] + g0.z + alpha * wvS[c0 + 2] + m * wmS[c0 + 2];
        float og = stage[r * 66 + c0 + 3] + g0.w + alpha * wvS[c0 + 3] + m * wmS[c0 + 3];
        float si = 1.f / (1.f + expf(-ig));
        float sf = 1.f / (1.f + expf(-fg));
        float so = 1.f / (1.f + expf(-og));
        float tg = tanhf(gg);
        int j = bn * 16 + jl;
        size_t ci = (size_t)b * HID + j;
        float c = sf * g_c[ci] + si * tg;
        g_c[ci] = c;
        float hnew = so * tanhf(c);

        float contrib = 0.f;
        if (more) {
            float dnx = deltas[b * T_SEQ + t + 1];
            float wdc = fmaf(dnx, wsumS[jl], bdecS[jl]);
            float gamma = expf(-fmaxf(wdc, 0.f));
            float hv = hnew * gamma;
            __half hi = __float2half_rn(hv);
            __half lo = __float2half_rn(hv - __half2float(hi));
            h2n[(size_t)b * KH2 + j] = hi;
            h2n[(size_t)b * KH2 + KHS + j] = lo;
            contrib = hv * wregS[jl];
        }
        #pragma unroll
        for (int off = 8; off; off >>= 1)
            contrib += __shfl_xor_sync(0xffffffff, contrib, off);
        if ((tid & 15) == 0) xh_i[i] = contrib;
    }

    if (more && (tid & 15) == 0) {
        #pragma unroll
        for (int i = 0; i < 8; i++) {
            int b = bm * 128 + ((tid + i * 256) >> 4);
            g_xh_part[1 - par][bn][b] = xh_i[i];   // (b, bn) owned by this block
        }
    }
}

// ---------------- finalize loss ----------------
__global__ void k_final(float* __restrict__ out) {
    if (threadIdx.x == 0) {
        float s = 0.f;
        for (int tt = 0; tt < T_SEQ; tt++) s += g_num[tt] / (g_den[tt] + 1e-5f);
        out[0] = s / (float)T_SEQ;
    }
}

extern "C" void kernel_launch(void* const* d_in, const int* in_sizes, int n_in,
                              void* d_out, int out_size)
{
    const float* V      = (const float*)d_in[0];
    const float* masks  = (const float*)d_in[1];
    const float* deltas = (const float*)d_in[2];
    const float* Wdec   = (const float*)d_in[3];
    const float* bdec   = (const float*)d_in[4];
    const float* Wreg   = (const float*)d_in[5];
    const float* breg   = (const float*)d_in[6];
    const float* Wih    = (const float*)d_in[7];
    const float* Whh    = (const float*)d_in[8];
    const float* bih    = (const float*)d_in[9];
    const float* bhh    = (const float*)d_in[10];
    float* out = (float*)d_out;

    cudaFuncSetAttribute(k_bigmma, cudaFuncAttributeMaxDynamicSharedMemorySize, SMEM_DYN);
    cudaFuncSetAttribute(k_gates,  cudaFuncAttributeMaxDynamicSharedMemorySize, SMEM_DYN);

    k_init<<<2048, 256>>>();
    k_wsum<<<HID, 256>>>(Wdec);

    k_convV<<<MROWS, 256>>>(V);
    k_convW<<<NG, 256>>>(Wih);
    k_convWh<<<NG, 256>>>(Whh);

    dim3 gB(NBN, MROWS / 128);     // (25, 1280); bn fastest -> A tile L2 reuse
    k_bigmma<<<gB, 256, SMEM_DYN>>>(bih, bhh);

    for (int t = 0; t < T_SEQ; t++) {
        dim3 g4(NBN, BATCH / 128); // (25, 64)
        k_gates<<<g4, 256, SMEM_DYN>>>(V, Wih, masks, deltas, bdec, Wreg, breg, out + 1, t);
    }
    k_final<<<1, 32>>>(out);
}

// round 9
// speedup vs baseline: 1.2111x; 1.2111x over previous
#include <cuda_runtime.h>
#include <cuda_fp16.h>
#include <math.h>
#include <stdint.h>

#define T_SEQ 20
#define NF    812
#define HID   400
#define NG    1600            // 4*HID
#define BATCH 8192
#define MROWS (BATCH * T_SEQ) // 163840
#define KP    832             // per-section K big GEMM (26*32)
#define K2    (2 * KP)        // 1664: [hi(V) | lo(V)] exact split
#define KH2   832             // gates K: [hi(400) | lo(400) | pad 32]
#define NCBIG (K2 / 32)       // 52
#define NCGAT (KH2 / 32)      // 26
#define NBN   (NG / 64)       // 25 n-tiles
#define NBM   (BATCH / 128)   // 64 gates m-tiles

// ---------------- device scratch ----------------
__device__ __half g_V2[(size_t)MROWS * K2];          // ~545 MB split values
__device__ __half g_W2[(size_t)NG * K2];             // W_ih [hi,hi] perm rows
__device__ __half g_Wh2[(size_t)NG * KH2];           // W_hh [hi,hi] perm rows
__device__ __half g_h2[2][(size_t)BATCH * KH2];      // [hi|lo] decayed h (dbl buf)
__device__ float g_G0[(size_t)MROWS * NG];           // ~1.05 GB perm gate pre-acts
__device__ float g_c [BATCH * HID];
__device__ float g_xh_part[2][NBN][BATCH];           // per-bn regression partials (dbl buf)
__device__ float g_loss_part[T_SEQ][NBM][2];         // deterministic loss partials
__device__ float g_wsum[HID];

// ---------------- PTX helpers ----------------
__device__ __forceinline__ uint32_t smem_u32(const void* p) {
    uint32_t a;
    asm("{ .reg .u64 t; cvta.to.shared.u64 t, %1; cvt.u32.u64 %0, t; }" : "=r"(a) : "l"(p));
    return a;
}
__device__ __forceinline__ void cp_async16(uint32_t saddr, const void* gaddr) {
    asm volatile("cp.async.cg.shared.global [%0], [%1], 16;\n" :: "r"(saddr), "l"(gaddr) : "memory");
}
__device__ __forceinline__ void ldsm_x4(uint32_t* r, uint32_t addr) {
    asm volatile("ldmatrix.sync.aligned.m8n8.x4.shared.b16 {%0,%1,%2,%3}, [%4];"
                 : "=r"(r[0]), "=r"(r[1]), "=r"(r[2]), "=r"(r[3]) : "r"(addr));
}
__device__ __forceinline__ void mma16816(float* d, const uint32_t* a, const uint32_t* b) {
    asm volatile(
        "mma.sync.aligned.m16n8k16.row.col.f32.f16.f16.f32 "
        "{%0,%1,%2,%3}, {%4,%5,%6,%7}, {%8,%9}, {%0,%1,%2,%3};"
        : "+f"(d[0]), "+f"(d[1]), "+f"(d[2]), "+f"(d[3])
        : "r"(a[0]), "r"(a[1]), "r"(a[2]), "r"(a[3]), "r"(b[0]), "r"(b[1]));
}

// smem: A 128 rows x 32 halves (80B stride), B 64 rows x 32 halves
#define A_STRIDE_B 80
#define A_TILE_B   (128 * A_STRIDE_B)    // 10240
#define B_TILE_B   (64 * A_STRIDE_B)     // 5120
#define BUF_B      (A_TILE_B + B_TILE_B) // 15360 per stage
#define NSTAGE     4
#define SMEM_DYN   (NSTAGE * BUF_B)      // 61440; epilogue stage 33792 fits

// ------- mma mainloop (BM=128, BN=64, BK=32, 8 warps 4x2, 4-stage) -------
__device__ __forceinline__ void gemm_mainloop(
    const __half* Abase, const __half* Bbase,
    int aStride, int bStride, int nChunks,
    uint32_t sbuf, float acc[2][4][4], int tid)
{
    int lane = tid & 31, w = tid >> 5;
    int wm = w & 3, wn = w >> 2;
    uint32_t aOffBase = (uint32_t)((wm * 32 + (lane & 15)) * A_STRIDE_B + ((lane >> 4) << 4));
    uint32_t bOffBase = (uint32_t)(A_TILE_B +
        (wn * 32 + ((lane >> 4) << 3) + (lane & 7)) * A_STRIDE_B + (((lane >> 3) & 1) << 4));

    int lrow = tid >> 2, lseg = tid & 3;

    // preload chunks 0..2
    #pragma unroll
    for (int pc = 0; pc < 3; pc++) {
        uint32_t dst = sbuf + pc * BUF_B;
        int koff = pc * 32;
        cp_async16(dst + lrow * A_STRIDE_B + lseg * 16,
                   Abase + (size_t)lrow * aStride + koff + lseg * 8);
        cp_async16(dst + (lrow + 64) * A_STRIDE_B + lseg * 16,
                   Abase + (size_t)(lrow + 64) * aStride + koff + lseg * 8);
        cp_async16(dst + A_TILE_B + lrow * A_STRIDE_B + lseg * 16,
                   Bbase + (size_t)lrow * bStride + koff + lseg * 8);
        asm volatile("cp.async.commit_group;\n" ::: "memory");
    }

    for (int c = 0; c < nChunks; c++) {
        // guarantee chunk c is resident: pending may only be chunks > c
        if (c + 3 <= nChunks) {
            asm volatile("cp.async.wait_group 2;\n" ::: "memory");
        } else if (c + 2 == nChunks) {
            asm volatile("cp.async.wait_group 1;\n" ::: "memory");
        } else {
            asm volatile("cp.async.wait_group 0;\n" ::: "memory");
        }
        __syncthreads();

        if (c + 3 < nChunks) {
            uint32_t dst = sbuf + ((c + 3) & 3) * BUF_B;
            int koff = (c + 3) * 32;
            cp_async16(dst + lrow * A_STRIDE_B + lseg * 16,
                       Abase + (size_t)lrow * aStride + koff + lseg * 8);
            cp_async16(dst + (lrow + 64) * A_STRIDE_B + lseg * 16,
                       Abase + (size_t)(lrow + 64) * aStride + koff + lseg * 8);
            cp_async16(dst + A_TILE_B + lrow * A_STRIDE_B + lseg * 16,
                       Bbase + (size_t)lrow * bStride + koff + lseg * 8);
            asm volatile("cp.async.commit_group;\n" ::: "memory");
        }

        uint32_t cur = sbuf + (c & 3) * BUF_B;
        #pragma unroll
        for (int kc = 0; kc < 2; kc++) {
            uint32_t aregs[2][4], bregs[2][4];
            ldsm_x4(aregs[0], cur + aOffBase + kc * 32);
            ldsm_x4(aregs[1], cur + aOffBase + 16 * A_STRIDE_B + kc * 32);
            ldsm_x4(bregs[0], cur + bOffBase + kc * 32);
            ldsm_x4(bregs[1], cur + bOffBase + 16 * A_STRIDE_B + kc * 32);
            #pragma unroll
            for (int mi = 0; mi < 2; mi++)
                #pragma unroll
                for (int ni = 0; ni < 4; ni++)
                    mma16816(acc[mi][ni], aregs[mi], &bregs[ni >> 1][(ni & 1) * 2]);
        }
    }
    __syncthreads();  // protect smem before epilogue staging reuses it
}

// stage acc -> smem fp32 [128][66]
__device__ __forceinline__ void stage_acc(float* stage, float acc[2][4][4], int tid) {
    int lane = tid & 31, w = tid >> 5;
    int wm = w & 3, wn = w >> 2;
    #pragma unroll
    for (int mi = 0; mi < 2; mi++)
        #pragma unroll
        for (int ni = 0; ni < 4; ni++) {
            int r0 = wm * 32 + mi * 16 + (lane >> 2);
            int cc = wn * 32 + ni * 8 + (lane & 3) * 2;
            *(float2*)&stage[r0 * 66 + cc]       = make_float2(acc[mi][ni][0], acc[mi][ni][1]);
            *(float2*)&stage[(r0 + 8) * 66 + cc] = make_float2(acc[mi][ni][2], acc[mi][ni][3]);
        }
}

// ---------------- init ----------------
__global__ void k_init() {
    long i = (long)blockIdx.x * blockDim.x + threadIdx.x;
    long stride = (long)gridDim.x * blockDim.x;
    for (long p = i; p < (long)BATCH * HID; p += stride) g_c[p] = 0.f;
    for (long p = i; p < 2L * BATCH * KH2; p += stride) ((__half*)g_h2)[p] = __float2half(0.f);
    for (long p = i; p < 2L * NBN * BATCH; p += stride) ((float*)g_xh_part)[p] = 0.f;
}

// ---------------- w_sum ----------------
__global__ void k_wsum(const float* __restrict__ Wd) {
    int row = blockIdx.x;
    __shared__ float red[256];
    float s = 0.f;
    for (int k = threadIdx.x; k < NF; k += 256) s += Wd[(size_t)row * NF + k];
    red[threadIdx.x] = s;
    __syncthreads();
    for (int off = 128; off; off >>= 1) {
        if (threadIdx.x < off) red[threadIdx.x] += red[threadIdx.x + off];
        __syncthreads();
    }
    if (threadIdx.x == 0) g_wsum[row] = red[0];
}

// ---------------- V2 = [hi(V) | lo(V)] (exact split, vectorized) ----------------
__global__ void k_convV(const float* __restrict__ V) {
    int r = blockIdx.x;
    const float4* src4 = (const float4*)(V + (size_t)r * NF);  // 203 float4 (NF%4==0)
    __half* dst = g_V2 + (size_t)r * K2;
    for (int k4 = threadIdx.x; k4 < NF / 4; k4 += 256) {
        float4 v = src4[k4];
        __half h0 = __float2half_rn(v.x), h1 = __float2half_rn(v.y);
        __half h2 = __float2half_rn(v.z), h3 = __float2half_rn(v.w);
        __half l0 = __float2half_rn(v.x - __half2float(h0));
        __half l1 = __float2half_rn(v.y - __half2float(h1));
        __half l2 = __float2half_rn(v.z - __half2float(h2));
        __half l3 = __float2half_rn(v.w - __half2float(h3));
        ((__half2*)dst)[k4 * 2]     = __halves2half2(h0, h1);
        ((__half2*)dst)[k4 * 2 + 1] = __halves2half2(h2, h3);
        ((__half2*)(dst + KP))[k4 * 2]     = __halves2half2(l0, l1);
        ((__half2*)(dst + KP))[k4 * 2 + 1] = __halves2half2(l2, l3);
    }
    if (threadIdx.x < KP - NF) {
        dst[NF + threadIdx.x] = __float2half(0.f);
        dst[KP + NF + threadIdx.x] = __float2half(0.f);
    }
}

// ---------------- W2 rows permuted (n = j*4+g), [hi, hi] ----------------
__global__ void k_convW(const float* __restrict__ Wih) {
    int n = blockIdx.x;
    int orig = (n & 3) * HID + (n >> 2);
    __half* dst = g_W2 + (size_t)n * K2;
    const float* src = Wih + (size_t)orig * (NF + 1);
    for (int k = threadIdx.x; k < KP; k += 256) {
        float w = (k < NF) ? src[k] : 0.f;
        __half hi = __float2half_rn(w);
        dst[k] = hi; dst[KP + k] = hi;
    }
}

// ---------------- Wh2 rows permuted, [hi(400), hi(400), pad 0] ----------------
__global__ void k_convWh(const float* __restrict__ Whh) {
    int n = blockIdx.x;
    int orig = (n & 3) * HID + (n >> 2);
    __half* dst = g_Wh2 + (size_t)n * KH2;
    const float* src = Whh + (size_t)orig * HID;
    for (int k = threadIdx.x; k < HID; k += 256) {
        __half hi = __float2half_rn(src[k]);
        dst[k] = hi; dst[HID + k] = hi;
    }
    if (threadIdx.x < KH2 - 2 * HID) dst[2 * HID + threadIdx.x] = __float2half(0.f);
}

// ---------------- big GEMM: G0(perm) = V2 @ W2^T + bias ----------------
__global__ __launch_bounds__(256, 3) void k_bigmma(const float* __restrict__ bih,
                                                   const float* __restrict__ bhh)
{
    extern __shared__ char smem[];
    uint32_t sbuf = smem_u32(smem);
    float* stage = (float*)smem;
    __shared__ float biasS[64];
    int tid = threadIdx.x;
    int bn = blockIdx.x, bm = blockIdx.y;

    if (tid < 64) {
        int np = bn * 64 + tid;
        int orig = (np & 3) * HID + (np >> 2);
        biasS[tid] = bih[orig] + bhh[orig];
    }

    float acc[2][4][4];
    #pragma unroll
    for (int a = 0; a < 2; a++)
        #pragma unroll
        for (int b = 0; b < 4; b++)
            #pragma unroll
            for (int c = 0; c < 4; c++) acc[a][b][c] = 0.f;

    gemm_mainloop(g_V2 + (size_t)(bm * 128) * K2, g_W2 + (size_t)(bn * 64) * K2,
                  K2, K2, NCBIG, sbuf, acc, tid);

    stage_acc(stage, acc, tid);
    __syncthreads();

    #pragma unroll
    for (int i = 0; i < 8; i++) {
        int lin = tid + i * 256;
        int r = lin >> 4, c4 = lin & 15;
        float4 v;
        v.x = stage[r * 66 + c4 * 4 + 0] + biasS[c4 * 4 + 0];
        v.y = stage[r * 66 + c4 * 4 + 1] + biasS[c4 * 4 + 1];
        v.z = stage[r * 66 + c4 * 4 + 2] + biasS[c4 * 4 + 2];
        v.w = stage[r * 66 + c4 * 4 + 3] + biasS[c4 * 4 + 3];
        *(float4*)&g_G0[(size_t)(bm * 128 + r) * NG + bn * 64 + c4 * 4] = v;
    }
}

// ---------------- recurrent GEMM + imputation prologue + fused LSTM cell ----------------
__global__ __launch_bounds__(256, 3) void k_gates(
    const float* __restrict__ V, const float* __restrict__ Wih,
    const float* __restrict__ masks, const float* __restrict__ deltas,
    const float* __restrict__ bdec, const float* __restrict__ Wreg,
    const float* __restrict__ breg, float* __restrict__ outImp, int t)
{
    extern __shared__ char smem[];
    uint32_t sbuf = smem_u32(smem);
    float* stage = (float*)smem;
    __shared__ float wvS[64], wmS[64];
    __shared__ float wsumS[16], bdecS[16], wregS[16];
    __shared__ float alphaS[128], mS[128];
    __shared__ float lossW[4][2];
    int tid = threadIdx.x;
    int bn = blockIdx.x, bm = blockIdx.y;
    int par = t & 1;

    if (tid < 64) {
        int np = bn * 64 + tid;
        int orig = (np & 3) * HID + (np >> 2);
        wvS[tid] = Wih[(size_t)orig * (NF + 1) + (NF - 1)];
        wmS[tid] = Wih[(size_t)orig * (NF + 1) + NF];
    }
    if (tid >= 64 && tid < 80) {
        int jl = tid - 64;
        int j = bn * 16 + jl;
        wsumS[jl] = g_wsum[j];
        bdecS[jl] = bdec[j];
        wregS[jl] = Wreg[j];
    }

    // ---- prologue: per-row regression xh, imputation, alpha, deterministic loss ----
    {
        float nloc = 0.f, dloc = 0.f;
        if (tid < 128) {
            int b = bm * 128 + tid;
            float xh = breg[0];
            #pragma unroll
            for (int p = 0; p < NBN; p++) xh += g_xh_part[par][p][b];
            float m  = masks[b * T_SEQ + t];
            float v  = V[((size_t)b * T_SEQ + t) * NF + (NF - 1)];
            float xvar = v * m + (1.f - m) * xh;
            alphaS[tid] = xvar - v;
            mS[tid] = m;
            if (bn == 0) {
                outImp[b * T_SEQ + t] = xvar;
                nloc = fabsf(xvar - xh) * m;
                dloc = m;
            }
        }
        if (bn == 0) {
            #pragma unroll
            for (int off = 16; off; off >>= 1) {
                nloc += __shfl_xor_sync(0xffffffff, nloc, off);
                dloc += __shfl_xor_sync(0xffffffff, dloc, off);
            }
            if (tid < 128 && (tid & 31) == 0) {
                lossW[tid >> 5][0] = nloc;
                lossW[tid >> 5][1] = dloc;
            }
        }
    }
    __syncthreads();
    if (bn == 0 && tid == 0) {
        float n4 = (lossW[0][0] + lossW[1][0]) + (lossW[2][0] + lossW[3][0]);
        float d4 = (lossW[0][1] + lossW[1][1]) + (lossW[2][1] + lossW[3][1]);
        g_loss_part[t][bm][0] = n4;
        g_loss_part[t][bm][1] = d4;
    }

    float acc[2][4][4];
    #pragma unroll
    for (int a = 0; a < 2; a++)
        #pragma unroll
        for (int b = 0; b < 4; b++)
            #pragma unroll
            for (int c = 0; c < 4; c++) acc[a][b][c] = 0.f;

    if (t > 0) {
        gemm_mainloop(g_h2[par] + (size_t)(bm * 128) * KH2, g_Wh2 + (size_t)(bn * 64) * KH2,
                      KH2, KH2, NCGAT, sbuf, acc, tid);
    } else {
        __syncthreads();
    }

    stage_acc(stage, acc, tid);
    __syncthreads();

    __half* h2n = g_h2[1 - par];
    bool more = (t + 1 < T_SEQ);
    float xh_i[8];
    #pragma unroll
    for (int i = 0; i < 8; i++) xh_i[i] = 0.f;

    #pragma unroll
    for (int i = 0; i < 8; i++) {
        int lin = tid + i * 256;       // 128 rows x 16 jl
        int r = lin >> 4, jl = lin & 15;
        int b = bm * 128 + r;
        float alpha = alphaS[r];
        float m = mS[r];
        int c0 = jl * 4;
        float4 g0 = *(const float4*)&g_G0[((size_t)b * T_SEQ + t) * NG + bn * 64 + c0];
        float ig = stage[r * 66 + c0 + 0] + g0.x + alpha * wvS[c0 + 0] + m * wmS[c0 + 0];
        float fg = stage[r * 66 + c0 + 1] + g0.y + alpha * wvS[c0 + 1] + m * wmS[c0 + 1];
        float gg = stage[r * 66 + c0 + 2] + g0.z + alpha * wvS[c0 + 2] + m * wmS[c0 + 2];
        float og = stage[r * 66 + c0 + 3] + g0.w + alpha * wvS[c0 + 3] + m * wmS[c0 + 3];
        float si = 1.f / (1.f + expf(-ig));
        float sf = 1.f / (1.f + expf(-fg));
        float so = 1.f / (1.f + expf(-og));
        float tg = tanhf(gg);
        int j = bn * 16 + jl;
        size_t ci = (size_t)b * HID + j;
        float c = sf * g_c[ci] + si * tg;
        g_c[ci] = c;
        float hnew = so * tanhf(c);

        float contrib = 0.f;
        if (more) {
            float dnx = deltas[b * T_SEQ + t + 1];
            float wdc = fmaf(dnx, wsumS[jl], bdecS[jl]);
            float gamma = expf(-fmaxf(wdc, 0.f));
            float hv = hnew * gamma;
            __half hi = __float2half_rn(hv);
            __half lo = __float2half_rn(hv - __half2float(hi));
            h2n[(size_t)b * KH2 + j] = hi;
            h2n[(size_t)b * KH2 + HID + j] = lo;
            contrib = hv * wregS[jl];
        }
        #pragma unroll
        for (int off = 8; off; off >>= 1)
            contrib += __shfl_xor_sync(0xffffffff, contrib, off);
        if ((tid & 15) == 0) xh_i[i] = contrib;
    }

    if (more && (tid & 15) == 0) {
        #pragma unroll
        for (int i = 0; i < 8; i++) {
            int b = bm * 128 + ((tid + i * 256) >> 4);
            g_xh_part[1 - par][bn][b] = xh_i[i];   // (b, bn) owned by this block
        }
    }
}

// ---------------- finalize loss (deterministic fixed-order reduction) ----------------
__global__ void k_final(float* __restrict__ out) {
    __shared__ float perT[T_SEQ];
    int tid = threadIdx.x;
    int t = tid >> 5, lane = tid & 31;
    if (t < T_SEQ) {
        float n = g_loss_part[t][lane][0] + g_loss_part[t][lane + 32][0];
        float d = g_loss_part[t][lane][1] + g_loss_part[t][lane + 32][1];
        #pragma unroll
        for (int off = 16; off; off >>= 1) {
            n += __shfl_xor_sync(0xffffffff, n, off);
            d += __shfl_xor_sync(0xffffffff, d, off);
        }
        if (lane == 0) perT[t] = n / (d + 1e-5f);
    }
    __syncthreads();
    if (tid == 0) {
        float s = 0.f;
        for (int tt = 0; tt < T_SEQ; tt++) s += perT[tt];
        out[0] = s / (float)T_SEQ;
    }
}

extern "C" void kernel_launch(void* const* d_in, const int* in_sizes, int n_in,
                              void* d_out, int out_size)
{
    const float* V      = (const float*)d_in[0];
    const float* masks  = (const float*)d_in[1];
    const float* deltas = (const float*)d_in[2];
    const float* Wdec   = (const float*)d_in[3];
    const float* bdec   = (const float*)d_in[4];
    const float* Wreg   = (const float*)d_in[5];
    const float* breg   = (const float*)d_in[6];
    const float* Wih    = (const float*)d_in[7];
    const float* Whh    = (const float*)d_in[8];
    const float* bih    = (const float*)d_in[9];
    const float* bhh    = (const float*)d_in[10];
    float* out = (float*)d_out;

    cudaFuncSetAttribute(k_bigmma, cudaFuncAttributeMaxDynamicSharedMemorySize, SMEM_DYN);
    cudaFuncSetAttribute(k_gates,  cudaFuncAttributeMaxDynamicSharedMemorySize, SMEM_DYN);

    k_init<<<2048, 256>>>();
    k_wsum<<<HID, 256>>>(Wdec);

    k_convV<<<MROWS, 256>>>(V);
    k_convW<<<NG, 256>>>(Wih);
    k_convWh<<<NG, 256>>>(Whh);

    dim3 gB(NBN, MROWS / 128);     // (25, 1280); bn fastest -> A tile L2 reuse
    k_bigmma<<<gB, 256, SMEM_DYN>>>(bih, bhh);

    for (int t = 0; t < T_SEQ; t++) {
        dim3 g4(NBN, NBM);         // (25, 64)
        k_gates<<<g4, 256, SMEM_DYN>>>(V, Wih, masks, deltas, bdec, Wreg, breg, out + 1, t);
    }
    k_final<<<1, T_SEQ * 32>>>(out);
}

// round 10
// speedup vs baseline: 1.2316x; 1.0169x over previous
#include <cuda_runtime.h>
#include <cuda_fp16.h>
#include <math.h>
#include <stdint.h>

#define T_SEQ 20
#define NF    812
#define HID   400
#define NG    1600            // 4*HID
#define BATCH 8192
#define MROWS (BATCH * T_SEQ) // 163840
#define KVS   832             // V per-section K (26*32)
#define KV    (2 * KVS)       // 1664: V2 row [hi | lo]
#define KHS   416             // h per-section K (13*32)
#define KH    (2 * KHS)       // 832: h2 row [hi | lo]
#define KC    (KV + KH)       // 2496 combined K
#define NCH_FULL (KC / 32)    // 78
#define NCH_T0   (KV / 32)    // 52 (h == 0 at t=0)
#define NBN   (NG / 64)       // 25 n-tiles
#define NBM   (BATCH / 128)   // 64 m-tiles

// ---------------- device scratch ----------------
__device__ __half g_V2[(size_t)MROWS * KV];          // ~545 MB, TIME-MAJOR rows (t*BATCH + b)
__device__ __half g_Wc[(size_t)NG * KC];             // ~8 MB combined [Wih|Wih|Whh|Whh] perm rows
__device__ __half g_h2[2][(size_t)BATCH * KH];       // [hi|lo] decayed h (dbl buf)
__device__ float g_c [BATCH * HID];
__device__ float g_xh_part[2][NBN][BATCH];           // per-bn regression partials (dbl buf)
__device__ float g_loss_part[T_SEQ][NBM][2];         // deterministic loss partials
__device__ float g_wsum[HID];

// ---------------- PTX helpers ----------------
__device__ __forceinline__ uint32_t smem_u32(const void* p) {
    uint32_t a;
    asm("{ .reg .u64 t; cvta.to.shared.u64 t, %1; cvt.u32.u64 %0, t; }" : "=r"(a) : "l"(p));
    return a;
}
__device__ __forceinline__ void cp_async16(uint32_t saddr, const void* gaddr) {
    asm volatile("cp.async.cg.shared.global [%0], [%1], 16;\n" :: "r"(saddr), "l"(gaddr) : "memory");
}
__device__ __forceinline__ void ldsm_x4(uint32_t* r, uint32_t addr) {
    asm volatile("ldmatrix.sync.aligned.m8n8.x4.shared.b16 {%0,%1,%2,%3}, [%4];"
                 : "=r"(r[0]), "=r"(r[1]), "=r"(r[2]), "=r"(r[3]) : "r"(addr));
}
__device__ __forceinline__ void mma16816(float* d, const uint32_t* a, const uint32_t* b) {
    asm volatile(
        "mma.sync.aligned.m16n8k16.row.col.f32.f16.f16.f32 "
        "{%0,%1,%2,%3}, {%4,%5,%6,%7}, {%8,%9}, {%0,%1,%2,%3};"
        : "+f"(d[0]), "+f"(d[1]), "+f"(d[2]), "+f"(d[3])
        : "r"(a[0]), "r"(a[1]), "r"(a[2]), "r"(a[3]), "r"(b[0]), "r"(b[1]));
}

// A gmem address for tile row + combined-k offset (V part or h part)
__device__ __forceinline__ const __half* a_addr(const __half* Av, const __half* Ah,
                                                int row, int koff) {
    return (koff < KV) ? (Av + (size_t)row * KV + koff)
                       : (Ah + (size_t)row * KH + (koff - KV));
}

// smem: A 128 rows x 32 halves (80B stride), B 64 rows x 32 halves
#define A_STRIDE_B 80
#define A_TILE_B   (128 * A_STRIDE_B)    // 10240
#define B_TILE_B   (64 * A_STRIDE_B)     // 5120
#define BUF_B      (A_TILE_B + B_TILE_B) // 15360 per stage
#define NSTAGE     4
#define SMEM_DYN   (NSTAGE * BUF_B)      // 61440; epilogue stage 33792 fits

// ------- mma mainloop (BM=128, BN=64, BK=32, 8 warps 4x2, 4-stage, dual-source A) -------
__device__ __forceinline__ void gemm_mainloop(
    const __half* Av, const __half* Ah, const __half* Bbase,
    int nChunks, uint32_t sbuf, float acc[2][4][4], int tid)
{
    int lane = tid & 31, w = tid >> 5;
    int wm = w & 3, wn = w >> 2;
    uint32_t aOffBase = (uint32_t)((wm * 32 + (lane & 15)) * A_STRIDE_B + ((lane >> 4) << 4));
    uint32_t bOffBase = (uint32_t)(A_TILE_B +
        (wn * 32 + ((lane >> 4) << 3) + (lane & 7)) * A_STRIDE_B + (((lane >> 3) & 1) << 4));

    int lrow = tid >> 2, lseg = tid & 3;

    // preload chunks 0..2
    #pragma unroll
    for (int pc = 0; pc < 3; pc++) {
        uint32_t dst = sbuf + pc * BUF_B;
        int koff = pc * 32 + lseg * 8;
        cp_async16(dst + lrow * A_STRIDE_B + lseg * 16, a_addr(Av, Ah, lrow, koff));
        cp_async16(dst + (lrow + 64) * A_STRIDE_B + lseg * 16, a_addr(Av, Ah, lrow + 64, koff));
        cp_async16(dst + A_TILE_B + lrow * A_STRIDE_B + lseg * 16,
                   Bbase + (size_t)lrow * KC + pc * 32 + lseg * 8);
        asm volatile("cp.async.commit_group;\n" ::: "memory");
    }

    for (int c = 0; c < nChunks; c++) {
        if (c + 3 <= nChunks) {
            asm volatile("cp.async.wait_group 2;\n" ::: "memory");
        } else if (c + 2 == nChunks) {
            asm volatile("cp.async.wait_group 1;\n" ::: "memory");
        } else {
            asm volatile("cp.async.wait_group 0;\n" ::: "memory");
        }
        __syncthreads();

        if (c + 3 < nChunks) {
            uint32_t dst = sbuf + ((c + 3) & 3) * BUF_B;
            int koff = (c + 3) * 32 + lseg * 8;
            cp_async16(dst + lrow * A_STRIDE_B + lseg * 16, a_addr(Av, Ah, lrow, koff));
            cp_async16(dst + (lrow + 64) * A_STRIDE_B + lseg * 16, a_addr(Av, Ah, lrow + 64, koff));
            cp_async16(dst + A_TILE_B + lrow * A_STRIDE_B + lseg * 16,
                       Bbase + (size_t)lrow * KC + (c + 3) * 32 + lseg * 8);
            asm volatile("cp.async.commit_group;\n" ::: "memory");
        }

        uint32_t cur = sbuf + (c & 3) * BUF_B;
        #pragma unroll
        for (int kc = 0; kc < 2; kc++) {
            uint32_t aregs[2][4], bregs[2][4];
            ldsm_x4(aregs[0], cur + aOffBase + kc * 32);
            ldsm_x4(aregs[1], cur + aOffBase + 16 * A_STRIDE_B + kc * 32);
            ldsm_x4(bregs[0], cur + bOffBase + kc * 32);
            ldsm_x4(bregs[1], cur + bOffBase + 16 * A_STRIDE_B + kc * 32);
            #pragma unroll
            for (int mi = 0; mi < 2; mi++)
                #pragma unroll
                for (int ni = 0; ni < 4; ni++)
                    mma16816(acc[mi][ni], aregs[mi], &bregs[ni >> 1][(ni & 1) * 2]);
        }
    }
    __syncthreads();  // protect smem before epilogue staging reuses it
}

// stage acc -> smem fp32 [128][66]
__device__ __forceinline__ void stage_acc(float* stage, float acc[2][4][4], int tid) {
    int lane = tid & 31, w = tid >> 5;
    int wm = w & 3, wn = w >> 2;
    #pragma unroll
    for (int mi = 0; mi < 2; mi++)
        #pragma unroll
        for (int ni = 0; ni < 4; ni++) {
            int r0 = wm * 32 + mi * 16 + (lane >> 2);
            int cc = wn * 32 + ni * 8 + (lane & 3) * 2;
            *(float2*)&stage[r0 * 66 + cc]       = make_float2(acc[mi][ni][0], acc[mi][ni][1]);
            *(float2*)&stage[(r0 + 8) * 66 + cc] = make_float2(acc[mi][ni][2], acc[mi][ni][3]);
        }
}

// ---------------- init ----------------
__global__ void k_init() {
    long i = (long)blockIdx.x * blockDim.x + threadIdx.x;
    long stride = (long)gridDim.x * blockDim.x;
    for (long p = i; p < (long)BATCH * HID; p += stride) g_c[p] = 0.f;
    for (long p = i; p < 2L * BATCH * KH; p += stride) ((__half*)g_h2)[p] = __float2half(0.f);
    for (long p = i; p < 2L * NBN * BATCH; p += stride) ((float*)g_xh_part)[p] = 0.f;
}

// ---------------- w_sum ----------------
__global__ void k_wsum(const float* __restrict__ Wd) {
    int row = blockIdx.x;
    __shared__ float red[256];
    float s = 0.f;
    for (int k = threadIdx.x; k < NF; k += 256) s += Wd[(size_t)row * NF + k];
    red[threadIdx.x] = s;
    __syncthreads();
    for (int off = 128; off; off >>= 1) {
        if (threadIdx.x < off) red[threadIdx.x] += red[threadIdx.x + off];
        __syncthreads();
    }
    if (threadIdx.x == 0) g_wsum[row] = red[0];
}

// ---------------- V2 = [hi(V) | lo(V)] time-major (row = t*BATCH + b) ----------------
__global__ void k_convV(const float* __restrict__ V) {
    int r = blockIdx.x;              // source row b*T_SEQ + t
    int b = r / T_SEQ, t = r % T_SEQ;
    const float4* src4 = (const float4*)(V + (size_t)r * NF);  // NF%4==0
    __half* dst = g_V2 + ((size_t)t * BATCH + b) * KV;
    for (int k4 = threadIdx.x; k4 < NF / 4; k4 += 256) {
        float4 v = src4[k4];
        __half h0 = __float2half_rn(v.x), h1 = __float2half_rn(v.y);
        __half h2 = __float2half_rn(v.z), h3 = __float2half_rn(v.w);
        __half l0 = __float2half_rn(v.x - __half2float(h0));
        __half l1 = __float2half_rn(v.y - __half2float(h1));
        __half l2 = __float2half_rn(v.z - __half2float(h2));
        __half l3 = __float2half_rn(v.w - __half2float(h3));
        ((__half2*)dst)[k4 * 2]     = __halves2half2(h0, h1);
        ((__half2*)dst)[k4 * 2 + 1] = __halves2half2(h2, h3);
        ((__half2*)(dst + KVS))[k4 * 2]     = __halves2half2(l0, l1);
        ((__half2*)(dst + KVS))[k4 * 2 + 1] = __halves2half2(l2, l3);
    }
    if (threadIdx.x < KVS - NF) {
        dst[NF + threadIdx.x] = __float2half(0.f);
        dst[KVS + NF + threadIdx.x] = __float2half(0.f);
    }
}

// ---------------- Wc rows permuted (n = j*4+g): [Wih | Wih | Whh | Whh] ----------------
__global__ void k_convWc(const float* __restrict__ Wih, const float* __restrict__ Whh) {
    int n = blockIdx.x;
    int orig = (n & 3) * HID + (n >> 2);
    __half* dst = g_Wc + (size_t)n * KC;
    const float* srcI = Wih + (size_t)orig * (NF + 1);
    const float* srcH = Whh + (size_t)orig * HID;
    for (int k = threadIdx.x; k < KVS; k += 256) {
        __half hv = __float2half_rn((k < NF) ? srcI[k] : 0.f);
        dst[k] = hv; dst[KVS + k] = hv;
    }
    for (int k = threadIdx.x; k < KHS; k += 256) {
        __half hv = __float2half_rn((k < HID) ? srcH[k] : 0.f);
        dst[KV + k] = hv; dst[KV + KHS + k] = hv;
    }
}

// ------- fused per-step kernel: [V|h] GEMM + imputation prologue + LSTM cell -------
__global__ __launch_bounds__(256, 3) void k_gates(
    const float* __restrict__ V, const float* __restrict__ Wih,
    const float* __restrict__ masks, const float* __restrict__ deltas,
    const float* __restrict__ bdec, const float* __restrict__ Wreg,
    const float* __restrict__ breg, const float* __restrict__ bih,
    const float* __restrict__ bhh, float* __restrict__ outImp, int t)
{
    extern __shared__ char smem[];
    uint32_t sbuf = smem_u32(smem);
    float* stage = (float*)smem;
    __shared__ float wvS[64], wmS[64], biasS[64];
    __shared__ float wsumS[16], bdecS[16], wregS[16];
    __shared__ float alphaS[128], mS[128];
    __shared__ float lossW[4][2];
    int tid = threadIdx.x;
    int bn = blockIdx.x, bm = blockIdx.y;
    int par = t & 1;

    if (tid < 64) {
        int np = bn * 64 + tid;
        int orig = (np & 3) * HID + (np >> 2);
        wvS[tid] = Wih[(size_t)orig * (NF + 1) + (NF - 1)];
        wmS[tid] = Wih[(size_t)orig * (NF + 1) + NF];
        biasS[tid] = bih[orig] + bhh[orig];
    }
    if (tid >= 64 && tid < 80) {
        int jl = tid - 64;
        int j = bn * 16 + jl;
        wsumS[jl] = g_wsum[j];
        bdecS[jl] = bdec[j];
        wregS[jl] = Wreg[j];
    }

    // ---- prologue: per-row regression xh, imputation, alpha, deterministic loss ----
    {
        float nloc = 0.f, dloc = 0.f;
        if (tid < 128) {
            int b = bm * 128 + tid;
            float xh = breg[0];
            #pragma unroll
            for (int p = 0; p < NBN; p++) xh += g_xh_part[par][p][b];
            float m  = masks[b * T_SEQ + t];
            float v  = V[((size_t)b * T_SEQ + t) * NF + (NF - 1)];
            float xvar = v * m + (1.f - m) * xh;
            alphaS[tid] = xvar - v;
            mS[tid] = m;
            if (bn == 0) {
                outImp[b * T_SEQ + t] = xvar;
                nloc = fabsf(xvar - xh) * m;
                dloc = m;
            }
        }
        if (bn == 0) {
            #pragma unroll
            for (int off = 16; off; off >>= 1) {
                nloc += __shfl_xor_sync(0xffffffff, nloc, off);
                dloc += __shfl_xor_sync(0xffffffff, dloc, off);
            }
            if (tid < 128 && (tid & 31) == 0) {
                lossW[tid >> 5][0] = nloc;
                lossW[tid >> 5][1] = dloc;
            }
        }
    }
    __syncthreads();
    if (bn == 0 && tid == 0) {
        float n4 = (lossW[0][0] + lossW[1][0]) + (lossW[2][0] + lossW[3][0]);
        float d4 = (lossW[0][1] + lossW[1][1]) + (lossW[2][1] + lossW[3][1]);
        g_loss_part[t][bm][0] = n4;
        g_loss_part[t][bm][1] = d4;
    }

    float acc[2][4][4];
    #pragma unroll
    for (int a = 0; a < 2; a++)
        #pragma unroll
        for (int b = 0; b < 4; b++)
            #pragma unroll
            for (int c = 0; c < 4; c++) acc[a][b][c] = 0.f;

    {
        const __half* Av = g_V2 + ((size_t)t * BATCH + bm * 128) * KV;
        const __half* Ah = g_h2[par] + (size_t)(bm * 128) * KH;
        const __half* Bb = g_Wc + (size_t)(bn * 64) * KC;
        int nChunks = (t > 0) ? NCH_FULL : NCH_T0;
        gemm_mainloop(Av, Ah, Bb, nChunks, sbuf, acc, tid);
    }

    stage_acc(stage, acc, tid);
    __syncthreads();

    __half* h2n = g_h2[1 - par];
    bool more = (t + 1 < T_SEQ);
    float xh_i[8];
    #pragma unroll
    for (int i = 0; i < 8; i++) xh_i[i] = 0.f;

    #pragma unroll
    for (int i = 0; i < 8; i++) {
        int lin = tid + i * 256;       // 128 rows x 16 jl
        int r = lin >> 4, jl = lin & 15;
        int b = bm * 128 + r;
        float alpha = alphaS[r];
        float m = mS[r];
        int c0 = jl * 4;
        float ig = stage[r * 66 + c0 + 0] + biasS[c0 + 0] + alpha * wvS[c0 + 0] + m * wmS[c0 + 0];
        float fg = stage[r * 66 + c0 + 1] + biasS[c0 + 1] + alpha * wvS[c0 + 1] + m * wmS[c0 + 1];
        float gg = stage[r * 66 + c0 + 2] + biasS[c0 + 2] + alpha * wvS[c0 + 2] + m * wmS[c0 + 2];
        float og = stage[r * 66 + c0 + 3] + biasS[c0 + 3] + alpha * wvS[c0 + 3] + m * wmS[c0 + 3];
        float si = 1.f / (1.f + expf(-ig));
        float sf = 1.f / (1.f + expf(-fg));
        float so = 1.f / (1.f + expf(-og));
        float tg = tanhf(gg);
        int j = bn * 16 + jl;
        size_t ci = (size_t)b * HID + j;
        float c = sf * g_c[ci] + si * tg;
        g_c[ci] = c;
        float hnew = so * tanhf(c);

        float contrib = 0.f;
        if (more) {
            float dnx = deltas[b * T_SEQ + t + 1];
            float wdc = fmaf(dnx, wsumS[jl], bdecS[jl]);
            float gamma = expf(-fmaxf(wdc, 0.f));
            float hv = hnew * gamma;
            __half hi = __float2half_rn(hv);
            __half lo = __float2half_rn(hv - __half2float(hi));
            h2n[(size_t)b * KH + j] = hi;            // hi section [0, 400)
            h2n[(size_t)b * KH + KHS + j] = lo;      // lo section [416, 816)
            contrib = hv * wregS[jl];
        }
        #pragma unroll
        for (int off = 8; off; off >>= 1)
            contrib += __shfl_xor_sync(0xffffffff, contrib, off);
        if ((tid & 15) == 0) xh_i[i] = contrib;
    }

    if (more && (tid & 15) == 0) {
        #pragma unroll
        for (int i = 0; i < 8; i++) {
            int b = bm * 128 + ((tid + i * 256) >> 4);
            g_xh_part[1 - par][bn][b] = xh_i[i];   // (b, bn) owned by this block
        }
    }
}

// ---------------- finalize loss (deterministic fixed-order reduction) ----------------
__global__ void k_final(float* __restrict__ out) {
    __shared__ float perT[T_SEQ];
    int tid = threadIdx.x;
    int t = tid >> 5, lane = tid & 31;
    if (t < T_SEQ) {
        float n = g_loss_part[t][lane][0] + g_loss_part[t][lane + 32][0];
        float d = g_loss_part[t][lane][1] + g_loss_part[t][lane + 32][1];
        #pragma unroll
        for (int off = 16; off; off >>= 1) {
            n += __shfl_xor_sync(0xffffffff, n, off);
            d += __shfl_xor_sync(0xffffffff, d, off);
        }
        if (lane == 0) perT[t] = n / (d + 1e-5f);
    }
    __syncthreads();
    if (tid == 0) {
        float s = 0.f;
        for (int tt = 0; tt < T_SEQ; tt++) s += perT[tt];
        out[0] = s / (float)T_SEQ;
    }
}

extern "C" void kernel_launch(void* const* d_in, const int* in_sizes, int n_in,
                              void* d_out, int out_size)
{
    const float* V      = (const float*)d_in[0];
    const float* masks  = (const float*)d_in[1];
    const float* deltas = (const float*)d_in[2];
    const float* Wdec   = (const float*)d_in[3];
    const float* bdec   = (const float*)d_in[4];
    const float* Wreg   = (const float*)d_in[5];
    const float* breg   = (const float*)d_in[6];
    const float* Wih    = (const float*)d_in[7];
    const float* Whh    = (const float*)d_in[8];
    const float* bih    = (const float*)d_in[9];
    const float* bhh    = (const float*)d_in[10];
    float* out = (float*)d_out;

    cudaFuncSetAttribute(k_gates, cudaFuncAttributeMaxDynamicSharedMemorySize, SMEM_DYN);

    k_init<<<2048, 256>>>();
    k_wsum<<<HID, 256>>>(Wdec);

    k_convV<<<MROWS, 256>>>(V);
    k_convWc<<<NG, 256>>>(Wih, Whh);

    for (int t = 0; t < T_SEQ; t++) {
        dim3 g4(NBN, NBM);         // (25, 64)
        k_gates<<<g4, 256, SMEM_DYN>>>(V, Wih, masks, deltas, bdec, Wreg, breg,
                                       bih, bhh, out + 1, t);
    }
    k_final<<<1, T_SEQ * 32>>>(out);
}

// round 11
// speedup vs baseline: 1.2984x; 1.0542x over previous
#include <cuda_runtime.h>
#include <cuda_fp16.h>
#include <math.h>
#include <stdint.h>

#define T_SEQ 20
#define NF    812
#define HID   400
#define NG    1600            // 4*HID
#define BATCH 8192
#define MROWS (BATCH * T_SEQ) // 163840
#define KVS   832             // V per-section K (26*32)
#define KV    (2 * KVS)       // 1664: V2 row [hi | lo]
#define KHS   416             // h per-section K (13*32)
#define KH    (2 * KHS)       // 832: h2 row [hi | lo]
#define KC    (KV + KH)       // 2496 combined K
#define NCH_FULL (KC / 32)    // 78
#define NCH_T0   (KV / 32)    // 52 (h == 0 at t=0)
#define NBN   (NG / 64)       // 25 n-tiles
#define NBM   (BATCH / 128)   // 64 m-tiles

// ---------------- device scratch ----------------
__device__ __half g_V2[(size_t)MROWS * KV];          // ~545 MB, TIME-MAJOR rows (t*BATCH + b)
__device__ __half g_Wc[(size_t)NG * KC];             // ~8 MB combined [Wih|Wih|Whh|Whh] perm rows
__device__ __half g_h2[2][(size_t)BATCH * KH];       // [hi|lo] decayed h (dbl buf)
__device__ float g_c [BATCH * HID];
__device__ float g_xh_part[2][NBN][BATCH];           // per-bn regression partials (dbl buf)
__device__ float g_loss_part[T_SEQ][NBM][2];         // deterministic loss partials
__device__ float g_wsum[HID];

// ---------------- fast math (MUFU-based; rel err ~1e-7, negligible vs 2.2e-5) ----------
__device__ __forceinline__ float fsigmoid(float x) {
    return __fdividef(1.f, 1.f + __expf(-x));
}
__device__ __forceinline__ float ftanh(float x) {
    return 1.f - __fdividef(2.f, 1.f + __expf(2.f * x));
}

// ---------------- PTX helpers ----------------
__device__ __forceinline__ uint32_t smem_u32(const void* p) {
    uint32_t a;
    asm("{ .reg .u64 t; cvta.to.shared.u64 t, %1; cvt.u32.u64 %0, t; }" : "=r"(a) : "l"(p));
    return a;
}
__device__ __forceinline__ void cp_async16(uint32_t saddr, const void* gaddr) {
    asm volatile("cp.async.cg.shared.global [%0], [%1], 16;\n" :: "r"(saddr), "l"(gaddr) : "memory");
}
__device__ __forceinline__ void ldsm_x4(uint32_t* r, uint32_t addr) {
    asm volatile("ldmatrix.sync.aligned.m8n8.x4.shared.b16 {%0,%1,%2,%3}, [%4];"
                 : "=r"(r[0]), "=r"(r[1]), "=r"(r[2]), "=r"(r[3]) : "r"(addr));
}
__device__ __forceinline__ void mma16816(float* d, const uint32_t* a, const uint32_t* b) {
    asm volatile(
        "mma.sync.aligned.m16n8k16.row.col.f32.f16.f16.f32 "
        "{%0,%1,%2,%3}, {%4,%5,%6,%7}, {%8,%9}, {%0,%1,%2,%3};"
        : "+f"(d[0]), "+f"(d[1]), "+f"(d[2]), "+f"(d[3])
        : "r"(a[0]), "r"(a[1]), "r"(a[2]), "r"(a[3]), "r"(b[0]), "r"(b[1]));
}

// A gmem address for tile row + combined-k offset (V part or h part)
__device__ __forceinline__ const __half* a_addr(const __half* Av, const __half* Ah,
                                                int row, int koff) {
    return (koff < KV) ? (Av + (size_t)row * KV + koff)
                       : (Ah + (size_t)row * KH + (koff - KV));
}

// smem: A 128 rows x 32 halves (80B stride), B 64 rows x 32 halves
#define A_STRIDE_B 80
#define A_TILE_B   (128 * A_STRIDE_B)    // 10240
#define B_TILE_B   (64 * A_STRIDE_B)     // 5120
#define BUF_B      (A_TILE_B + B_TILE_B) // 15360 per stage
#define NSTAGE     4
#define SMEM_DYN   (NSTAGE * BUF_B)      // 61440; epilogue stage 33792 fits

// ------- preload first 3 chunks (issued BEFORE the prologue to overlap latency) -------
__device__ __forceinline__ void gemm_preload(
    const __half* Av, const __half* Ah, const __half* Bbase,
    uint32_t sbuf, int tid)
{
    int lrow = tid >> 2, lseg = tid & 3;
    #pragma unroll
    for (int pc = 0; pc < 3; pc++) {
        uint32_t dst = sbuf + pc * BUF_B;
        int koff = pc * 32 + lseg * 8;
        cp_async16(dst + lrow * A_STRIDE_B + lseg * 16, a_addr(Av, Ah, lrow, koff));
        cp_async16(dst + (lrow + 64) * A_STRIDE_B + lseg * 16, a_addr(Av, Ah, lrow + 64, koff));
        cp_async16(dst + A_TILE_B + lrow * A_STRIDE_B + lseg * 16,
                   Bbase + (size_t)lrow * KC + pc * 32 + lseg * 8);
        asm volatile("cp.async.commit_group;\n" ::: "memory");
    }
}

// ------- mma mainloop body (BM=128, BN=64, BK=32, 8 warps 4x2, 4-stage) -------
__device__ __forceinline__ void gemm_run(
    const __half* Av, const __half* Ah, const __half* Bbase,
    int nChunks, uint32_t sbuf, float acc[2][4][4], int tid)
{
    int lane = tid & 31, w = tid >> 5;
    int wm = w & 3, wn = w >> 2;
    uint32_t aOffBase = (uint32_t)((wm * 32 + (lane & 15)) * A_STRIDE_B + ((lane >> 4) << 4));
    uint32_t bOffBase = (uint32_t)(A_TILE_B +
        (wn * 32 + ((lane >> 4) << 3) + (lane & 7)) * A_STRIDE_B + (((lane >> 3) & 1) << 4));

    int lrow = tid >> 2, lseg = tid & 3;

    for (int c = 0; c < nChunks; c++) {
        if (c + 3 <= nChunks) {
            asm volatile("cp.async.wait_group 2;\n" ::: "memory");
        } else if (c + 2 == nChunks) {
            asm volatile("cp.async.wait_group 1;\n" ::: "memory");
        } else {
            asm volatile("cp.async.wait_group 0;\n" ::: "memory");
        }
        __syncthreads();

        if (c + 3 < nChunks) {
            uint32_t dst = sbuf + ((c + 3) & 3) * BUF_B;
            int koff = (c + 3) * 32 + lseg * 8;
            cp_async16(dst + lrow * A_STRIDE_B + lseg * 16, a_addr(Av, Ah, lrow, koff));
            cp_async16(dst + (lrow + 64) * A_STRIDE_B + lseg * 16, a_addr(Av, Ah, lrow + 64, koff));
            cp_async16(dst + A_TILE_B + lrow * A_STRIDE_B + lseg * 16,
                       Bbase + (size_t)lrow * KC + (c + 3) * 32 + lseg * 8);
            asm volatile("cp.async.commit_group;\n" ::: "memory");
        }

        uint32_t cur = sbuf + (c & 3) * BUF_B;
        #pragma unroll
        for (int kc = 0; kc < 2; kc++) {
            uint32_t aregs[2][4], bregs[2][4];
            ldsm_x4(aregs[0], cur + aOffBase + kc * 32);
            ldsm_x4(aregs[1], cur + aOffBase + 16 * A_STRIDE_B + kc * 32);
            ldsm_x4(bregs[0], cur + bOffBase + kc * 32);
            ldsm_x4(bregs[1], cur + bOffBase + 16 * A_STRIDE_B + kc * 32);
            #pragma unroll
            for (int mi = 0; mi < 2; mi++)
                #pragma unroll
                for (int ni = 0; ni < 4; ni++)
                    mma16816(acc[mi][ni], aregs[mi], &bregs[ni >> 1][(ni & 1) * 2]);
        }
    }
    __syncthreads();  // protect smem before epilogue staging reuses it
}

// stage acc -> smem fp32 [128][66]
__device__ __forceinline__ void stage_acc(float* stage, float acc[2][4][4], int tid) {
    int lane = tid & 31, w = tid >> 5;
    int wm = w & 3, wn = w >> 2;
    #pragma unroll
    for (int mi = 0; mi < 2; mi++)
        #pragma unroll
        for (int ni = 0; ni < 4; ni++) {
            int r0 = wm * 32 + mi * 16 + (lane >> 2);
            int cc = wn * 32 + ni * 8 + (lane & 3) * 2;
            *(float2*)&stage[r0 * 66 + cc]       = make_float2(acc[mi][ni][0], acc[mi][ni][1]);
            *(float2*)&stage[(r0 + 8) * 66 + cc] = make_float2(acc[mi][ni][2], acc[mi][ni][3]);
        }
}

// ---------------- init ----------------
__global__ void k_init() {
    long i = (long)blockIdx.x * blockDim.x + threadIdx.x;
    long stride = (long)gridDim.x * blockDim.x;
    for (long p = i; p < (long)BATCH * HID; p += stride) g_c[p] = 0.f;
    for (long p = i; p < 2L * BATCH * KH; p += stride) ((__half*)g_h2)[p] = __float2half(0.f);
    for (long p = i; p < 2L * NBN * BATCH; p += stride) ((float*)g_xh_part)[p] = 0.f;
}

// ---------------- w_sum ----------------
__global__ void k_wsum(const float* __restrict__ Wd) {
    int row = blockIdx.x;
    __shared__ float red[256];
    float s = 0.f;
    for (int k = threadIdx.x; k < NF; k += 256) s += Wd[(size_t)row * NF + k];
    red[threadIdx.x] = s;
    __syncthreads();
    for (int off = 128; off; off >>= 1) {
        if (threadIdx.x < off) red[threadIdx.x] += red[threadIdx.x + off];
        __syncthreads();
    }
    if (threadIdx.x == 0) g_wsum[row] = red[0];
}

// ---------------- V2 = [hi(V) | lo(V)] time-major (row = t*BATCH + b) ----------------
__global__ void k_convV(const float* __restrict__ V) {
    int r = blockIdx.x;              // source row b*T_SEQ + t
    int b = r / T_SEQ, t = r % T_SEQ;
    const float4* src4 = (const float4*)(V + (size_t)r * NF);  // NF%4==0
    __half* dst = g_V2 + ((size_t)t * BATCH + b) * KV;
    for (int k4 = threadIdx.x; k4 < NF / 4; k4 += 256) {
        float4 v = src4[k4];
        __half h0 = __float2half_rn(v.x), h1 = __float2half_rn(v.y);
        __half h2 = __float2half_rn(v.z), h3 = __float2half_rn(v.w);
        __half l0 = __float2half_rn(v.x - __half2float(h0));
        __half l1 = __float2half_rn(v.y - __half2float(h1));
        __half l2 = __float2half_rn(v.z - __half2float(h2));
        __half l3 = __float2half_rn(v.w - __half2float(h3));
        ((__half2*)dst)[k4 * 2]     = __halves2half2(h0, h1);
        ((__half2*)dst)[k4 * 2 + 1] = __halves2half2(h2, h3);
        ((__half2*)(dst + KVS))[k4 * 2]     = __halves2half2(l0, l1);
        ((__half2*)(dst + KVS))[k4 * 2 + 1] = __halves2half2(l2, l3);
    }
    if (threadIdx.x < KVS - NF) {
        dst[NF + threadIdx.x] = __float2half(0.f);
        dst[KVS + NF + threadIdx.x] = __float2half(0.f);
    }
}

// ---------------- Wc rows permuted (n = j*4+g): [Wih | Wih | Whh | Whh] ----------------
__global__ void k_convWc(const float* __restrict__ Wih, const float* __restrict__ Whh) {
    int n = blockIdx.x;
    int orig = (n & 3) * HID + (n >> 2);
    __half* dst = g_Wc + (size_t)n * KC;
    const float* srcI = Wih + (size_t)orig * (NF + 1);
    const float* srcH = Whh + (size_t)orig * HID;
    for (int k = threadIdx.x; k < KVS; k += 256) {
        __half hv = __float2half_rn((k < NF) ? srcI[k] : 0.f);
        dst[k] = hv; dst[KVS + k] = hv;
    }
    for (int k = threadIdx.x; k < KHS; k += 256) {
        __half hv = __float2half_rn((k < HID) ? srcH[k] : 0.f);
        dst[KV + k] = hv; dst[KV + KHS + k] = hv;
    }
}

// ------- fused per-step kernel: [V|h] GEMM + imputation prologue + LSTM cell -------
__global__ __launch_bounds__(256, 3) void k_gates(
    const float* __restrict__ V, const float* __restrict__ Wih,
    const float* __restrict__ masks, const float* __restrict__ deltas,
    const float* __restrict__ bdec, const float* __restrict__ Wreg,
    const float* __restrict__ breg, const float* __restrict__ bih,
    const float* __restrict__ bhh, float* __restrict__ outImp, int t)
{
    extern __shared__ char smem[];
    uint32_t sbuf = smem_u32(smem);
    float* stage = (float*)smem;
    __shared__ float wvS[64], wmS[64], biasS[64];
    __shared__ float wsumS[16], bdecS[16], wregS[16];
    __shared__ float alphaS[128], mS[128];
    __shared__ float lossW[4][2];
    int tid = threadIdx.x;
    int bn = blockIdx.x, bm = blockIdx.y;
    int par = t & 1;

    // ---- issue first pipeline stages immediately (overlaps everything below) ----
    const __half* Av = g_V2 + ((size_t)t * BATCH + bm * 128) * KV;
    const __half* Ah = g_h2[par] + (size_t)(bm * 128) * KH;
    const __half* Bb = g_Wc + (size_t)(bn * 64) * KC;
    int nChunks = (t > 0) ? NCH_FULL : NCH_T0;
    gemm_preload(Av, Ah, Bb, sbuf, tid);

    if (tid < 64) {
        int np = bn * 64 + tid;
        int orig = (np & 3) * HID + (np >> 2);
        wvS[tid] = Wih[(size_t)orig * (NF + 1) + (NF - 1)];
        wmS[tid] = Wih[(size_t)orig * (NF + 1) + NF];
        biasS[tid] = bih[orig] + bhh[orig];
    }
    if (tid >= 64 && tid < 80) {
        int jl = tid - 64;
        int j = bn * 16 + jl;
        wsumS[jl] = g_wsum[j];
        bdecS[jl] = bdec[j];
        wregS[jl] = Wreg[j];
    }

    // ---- prologue: per-row regression xh, imputation, alpha, deterministic loss ----
    {
        float nloc = 0.f, dloc = 0.f;
        if (tid < 128) {
            int b = bm * 128 + tid;
            float xh = breg[0];
            #pragma unroll
            for (int p = 0; p < NBN; p++) xh += g_xh_part[par][p][b];
            float m  = masks[b * T_SEQ + t];
            float v  = V[((size_t)b * T_SEQ + t) * NF + (NF - 1)];
            float xvar = v * m + (1.f - m) * xh;
            alphaS[tid] = xvar - v;
            mS[tid] = m;
            if (bn == 0) {
                outImp[b * T_SEQ + t] = xvar;
                nloc = fabsf(xvar - xh) * m;
                dloc = m;
            }
        }
        if (bn == 0) {
            #pragma unroll
            for (int off = 16; off; off >>= 1) {
                nloc += __shfl_xor_sync(0xffffffff, nloc, off);
                dloc += __shfl_xor_sync(0xffffffff, dloc, off);
            }
            if (tid < 128 && (tid & 31) == 0) {
                lossW[tid >> 5][0] = nloc;
                lossW[tid >> 5][1] = dloc;
            }
        }
    }
    __syncthreads();
    if (bn == 0 && tid == 0) {
        float n4 = (lossW[0][0] + lossW[1][0]) + (lossW[2][0] + lossW[3][0]);
        float d4 = (lossW[0][1] + lossW[1][1]) + (lossW[2][1] + lossW[3][1]);
        g_loss_part[t][bm][0] = n4;
        g_loss_part[t][bm][1] = d4;
    }

    float acc[2][4][4];
    #pragma unroll
    for (int a = 0; a < 2; a++)
        #pragma unroll
        for (int b = 0; b < 4; b++)
            #pragma unroll
            for (int c = 0; c < 4; c++) acc[a][b][c] = 0.f;

    gemm_run(Av, Ah, Bb, nChunks, sbuf, acc, tid);

    stage_acc(stage, acc, tid);
    __syncthreads();

    __half* h2n = g_h2[1 - par];
    bool more = (t + 1 < T_SEQ);
    float xh_i[8];
    #pragma unroll
    for (int i = 0; i < 8; i++) xh_i[i] = 0.f;

    #pragma unroll
    for (int i = 0; i < 8; i++) {
        int lin = tid + i * 256;       // 128 rows x 16 jl
        int r = lin >> 4, jl = lin & 15;
        int b = bm * 128 + r;
        float alpha = alphaS[r];
        float m = mS[r];
        int c0 = jl * 4;
        float ig = stage[r * 66 + c0 + 0] + biasS[c0 + 0] + alpha * wvS[c0 + 0] + m * wmS[c0 + 0];
        float fg = stage[r * 66 + c0 + 1] + biasS[c0 + 1] + alpha * wvS[c0 + 1] + m * wmS[c0 + 1];
        float gg = stage[r * 66 + c0 + 2] + biasS[c0 + 2] + alpha * wvS[c0 + 2] + m * wmS[c0 + 2];
        float og = stage[r * 66 + c0 + 3] + biasS[c0 + 3] + alpha * wvS[c0 + 3] + m * wmS[c0 + 3];
        float si = fsigmoid(ig);
        float sf = fsigmoid(fg);
        float so = fsigmoid(og);
        float tg = ftanh(gg);
        int j = bn * 16 + jl;
        size_t ci = (size_t)b * HID + j;
        float c = sf * g_c[ci] + si * tg;
        g_c[ci] = c;
        float hnew = so * ftanh(c);

        float contrib = 0.f;
        if (more) {
            float dnx = deltas[b * T_SEQ + t + 1];
            float wdc = fmaf(dnx, wsumS[jl], bdecS[jl]);
            float gamma = __expf(-fmaxf(wdc, 0.f));
            float hv = hnew * gamma;
            __half hi = __float2half_rn(hv);
            __half lo = __float2half_rn(hv - __half2float(hi));
            h2n[(size_t)b * KH + j] = hi;            // hi section [0, 400)
            h2n[(size_t)b * KH + KHS + j] = lo;      // lo section [416, 816)
            contrib = hv * wregS[jl];
        }
        #pragma unroll
        for (int off = 8; off; off >>= 1)
            contrib += __shfl_xor_sync(0xffffffff, contrib, off);
        if ((tid & 15) == 0) xh_i[i] = contrib;
    }

    if (more && (tid & 15) == 0) {
        #pragma unroll
        for (int i = 0; i < 8; i++) {
            int b = bm * 128 + ((tid + i * 256) >> 4);
            g_xh_part[1 - par][bn][b] = xh_i[i];   // (b, bn) owned by this block
        }
    }
}

// ---------------- finalize loss (deterministic fixed-order reduction) ----------------
__global__ void k_final(float* __restrict__ out) {
    __shared__ float perT[T_SEQ];
    int tid = threadIdx.x;
    int t = tid >> 5, lane = tid & 31;
    if (t < T_SEQ) {
        float n = g_loss_part[t][lane][0] + g_loss_part[t][lane + 32][0];
        float d = g_loss_part[t][lane][1] + g_loss_part[t][lane + 32][1];
        #pragma unroll
        for (int off = 16; off; off >>= 1) {
            n += __shfl_xor_sync(0xffffffff, n, off);
            d += __shfl_xor_sync(0xffffffff, d, off);
        }
        if (lane == 0) perT[t] = n / (d + 1e-5f);
    }
    __syncthreads();
    if (tid == 0) {
        float s = 0.f;
        for (int tt = 0; tt < T_SEQ; tt++) s += perT[tt];
        out[0] = s / (float)T_SEQ;
    }
}

extern "C" void kernel_launch(void* const* d_in, const int* in_sizes, int n_in,
                              void* d_out, int out_size)
{
    const float* V      = (const float*)d_in[0];
    const float* masks  = (const float*)d_in[1];
    const float* deltas = (const float*)d_in[2];
    const float* Wdec   = (const float*)d_in[3];
    const float* bdec   = (const float*)d_in[4];
    const float* Wreg   = (const float*)d_in[5];
    const float* breg   = (const float*)d_in[6];
    const float* Wih    = (const float*)d_in[7];
    const float* Whh    = (const float*)d_in[8];
    const float* bih    = (const float*)d_in[9];
    const float* bhh    = (const float*)d_in[10];
    float* out = (float*)d_out;

    cudaFuncSetAttribute(k_gates, cudaFuncAttributeMaxDynamicSharedMemorySize, SMEM_DYN);

    k_init<<<2048, 256>>>();
    k_wsum<<<HID, 256>>>(Wdec);

    k_convV<<<MROWS, 256>>>(V);
    k_convWc<<<NG, 256>>>(Wih, Whh);

    for (int t = 0; t < T_SEQ; t++) {
        dim3 g4(NBN, NBM);         // (25, 64)
        k_gates<<<g4, 256, SMEM_DYN>>>(V, Wih, masks, deltas, bdec, Wreg, breg,
                                       bih, bhh, out + 1, t);
    }
    k_final<<<1, T_SEQ * 32>>>(out);
}

// round 12
// speedup vs baseline: 1.2999x; 1.0012x over previous
#include <cuda_runtime.h>
#include <cuda_fp16.h>
#include <math.h>
#include <stdint.h>

#define T_SEQ 20
#define NF    812
#define HID   400
#define NG    1600            // 4*HID
#define BATCH 8192
#define MROWS (BATCH * T_SEQ) // 163840
#define KVS   832             // V per-section K (26*32)
#define KV    (2 * KVS)       // 1664: V2 row [hi | lo]
#define KHS   416             // h per-section K (13*32)
#define KH    (2 * KHS)       // 832: h2 row [hi | lo]
#define KC    (KV + KH)       // 2496 combined K
#define NCH_FULL (KC / 32)    // 78
#define NCH_T0   (KV / 32)    // 52 (h == 0 at t=0)
#define NBN   (NG / 64)       // 25 n-tiles
#define NBM   (BATCH / 128)   // 64 m-tiles

// ---------------- device scratch ----------------
__device__ __half g_V2[(size_t)MROWS * KV];          // ~545 MB, TIME-MAJOR rows (t*BATCH + b)
__device__ __half g_Wc[(size_t)NG * KC];             // ~8 MB combined [Wih|Wih|Whh|Whh] perm rows
__device__ __half g_h2[2][(size_t)BATCH * KH];       // [hi|lo] decayed h (dbl buf)
__device__ float g_c [BATCH * HID];
__device__ float g_xh_part[2][NBN][BATCH];           // per-bn regression partials (dbl buf)
__device__ float g_loss_part[T_SEQ][NBM][2];         // deterministic loss partials
__device__ float g_wsum[HID];

// ---------------- fast math (MUFU-based; rel err ~1e-7, negligible vs 2.2e-5) ----------
__device__ __forceinline__ float fsigmoid(float x) {
    return __fdividef(1.f, 1.f + __expf(-x));
}
__device__ __forceinline__ float ftanh(float x) {
    return 1.f - __fdividef(2.f, 1.f + __expf(2.f * x));
}

// ---------------- PTX helpers ----------------
__device__ __forceinline__ uint32_t smem_u32(const void* p) {
    uint32_t a;
    asm("{ .reg .u64 t; cvta.to.shared.u64 t, %1; cvt.u32.u64 %0, t; }" : "=r"(a) : "l"(p));
    return a;
}
__device__ __forceinline__ void cp_async16(uint32_t saddr, const void* gaddr) {
    asm volatile("cp.async.cg.shared.global [%0], [%1], 16;\n" :: "r"(saddr), "l"(gaddr) : "memory");
}
__device__ __forceinline__ void ldsm_x4(uint32_t* r, uint32_t addr) {
    asm volatile("ldmatrix.sync.aligned.m8n8.x4.shared.b16 {%0,%1,%2,%3}, [%4];"
                 : "=r"(r[0]), "=r"(r[1]), "=r"(r[2]), "=r"(r[3]) : "r"(addr));
}
__device__ __forceinline__ void mma16816(float* d, const uint32_t* a, const uint32_t* b) {
    asm volatile(
        "mma.sync.aligned.m16n8k16.row.col.f32.f16.f16.f32 "
        "{%0,%1,%2,%3}, {%4,%5,%6,%7}, {%8,%9}, {%0,%1,%2,%3};"
        : "+f"(d[0]), "+f"(d[1]), "+f"(d[2]), "+f"(d[3])
        : "r"(a[0]), "r"(a[1]), "r"(a[2]), "r"(a[3]), "r"(b[0]), "r"(b[1]));
}

// A gmem address for tile row + combined-k offset (V part or h part)
__device__ __forceinline__ const __half* a_addr(const __half* Av, const __half* Ah,
                                                int row, int koff) {
    return (koff < KV) ? (Av + (size_t)row * KV + koff)
                       : (Ah + (size_t)row * KH + (koff - KV));
}

// smem: A 128 rows x 32 halves (80B stride), B 64 rows x 32 halves
#define A_STRIDE_B 80
#define A_TILE_B   (128 * A_STRIDE_B)    // 10240
#define B_TILE_B   (64 * A_STRIDE_B)     // 5120
#define BUF_B      (A_TILE_B + B_TILE_B) // 15360 per stage
#define NSTAGE     4
#define SMEM_DYN   (NSTAGE * BUF_B)      // 61440; epilogue stage 33792 fits

// ------- preload first 3 chunks (issued BEFORE the prologue to overlap latency) -------
__device__ __forceinline__ void gemm_preload(
    const __half* Av, const __half* Ah, const __half* Bbase,
    uint32_t sbuf, int tid)
{
    int lrow = tid >> 2, lseg = tid & 3;
    #pragma unroll
    for (int pc = 0; pc < 3; pc++) {
        uint32_t dst = sbuf + pc * BUF_B;
        int koff = pc * 32 + lseg * 8;
        cp_async16(dst + lrow * A_STRIDE_B + lseg * 16, a_addr(Av, Ah, lrow, koff));
        cp_async16(dst + (lrow + 64) * A_STRIDE_B + lseg * 16, a_addr(Av, Ah, lrow + 64, koff));
        cp_async16(dst + A_TILE_B + lrow * A_STRIDE_B + lseg * 16,
                   Bbase + (size_t)lrow * KC + pc * 32 + lseg * 8);
        asm volatile("cp.async.commit_group;\n" ::: "memory");
    }
}

// ------- mma mainloop body (BM=128, BN=64, BK=32, 8 warps 4x2, 4-stage) -------
__device__ __forceinline__ void gemm_run(
    const __half* Av, const __half* Ah, const __half* Bbase,
    int nChunks, uint32_t sbuf, float acc[2][4][4], int tid)
{
    int lane = tid & 31, w = tid >> 5;
    int wm = w & 3, wn = w >> 2;
    uint32_t aOffBase = (uint32_t)((wm * 32 + (lane & 15)) * A_STRIDE_B + ((lane >> 4) << 4));
    uint32_t bOffBase = (uint32_t)(A_TILE_B +
        (wn * 32 + ((lane >> 4) << 3) + (lane & 7)) * A_STRIDE_B + (((lane >> 3) & 1) << 4));

    int lrow = tid >> 2, lseg = tid & 3;

    for (int c = 0; c < nChunks; c++) {
        if (c + 3 <= nChunks) {
            asm volatile("cp.async.wait_group 2;\n" ::: "memory");
        } else if (c + 2 == nChunks) {
            asm volatile("cp.async.wait_group 1;\n" ::: "memory");
        } else {
            asm volatile("cp.async.wait_group 0;\n" ::: "memory");
        }
        __syncthreads();

        if (c + 3 < nChunks) {
            uint32_t dst = sbuf + ((c + 3) & 3) * BUF_B;
            int koff = (c + 3) * 32 + lseg * 8;
            cp_async16(dst + lrow * A_STRIDE_B + lseg * 16, a_addr(Av, Ah, lrow, koff));
            cp_async16(dst + (lrow + 64) * A_STRIDE_B + lseg * 16, a_addr(Av, Ah, lrow + 64, koff));
            cp_async16(dst + A_TILE_B + lrow * A_STRIDE_B + lseg * 16,
                       Bbase + (size_t)lrow * KC + (c + 3) * 32 + lseg * 8);
            asm volatile("cp.async.commit_group;\n" ::: "memory");
        }

        uint32_t cur = sbuf + (c & 3) * BUF_B;
        #pragma unroll
        for (int kc = 0; kc < 2; kc++) {
            uint32_t aregs[2][4], bregs[2][4];
            ldsm_x4(aregs[0], cur + aOffBase + kc * 32);
            ldsm_x4(aregs[1], cur + aOffBase + 16 * A_STRIDE_B + kc * 32);
            ldsm_x4(bregs[0], cur + bOffBase + kc * 32);
            ldsm_x4(bregs[1], cur + bOffBase + 16 * A_STRIDE_B + kc * 32);
            #pragma unroll
            for (int mi = 0; mi < 2; mi++)
                #pragma unroll
                for (int ni = 0; ni < 4; ni++)
                    mma16816(acc[mi][ni], aregs[mi], &bregs[ni >> 1][(ni & 1) * 2]);
        }
    }
    __syncthreads();  // protect smem before epilogue staging reuses it
}

// stage acc -> smem fp32 [128][66]
__device__ __forceinline__ void stage_acc(float* stage, float acc[2][4][4], int tid) {
    int lane = tid & 31, w = tid >> 5;
    int wm = w & 3, wn = w >> 2;
    #pragma unroll
    for (int mi = 0; mi < 2; mi++)
        #pragma unroll
        for (int ni = 0; ni < 4; ni++) {
            int r0 = wm * 32 + mi * 16 + (lane >> 2);
            int cc = wn * 32 + ni * 8 + (lane & 3) * 2;
            *(float2*)&stage[r0 * 66 + cc]       = make_float2(acc[mi][ni][0], acc[mi][ni][1]);
            *(float2*)&stage[(r0 + 8) * 66 + cc] = make_float2(acc[mi][ni][2], acc[mi][ni][3]);
        }
}

// ---------------- init ----------------
__global__ void k_init() {
    long i = (long)blockIdx.x * blockDim.x + threadIdx.x;
    long stride = (long)gridDim.x * blockDim.x;
    for (long p = i; p < (long)BATCH * HID; p += stride) g_c[p] = 0.f;
    for (long p = i; p < 2L * BATCH * KH; p += stride) ((__half*)g_h2)[p] = __float2half(0.f);
    for (long p = i; p < 2L * NBN * BATCH; p += stride) ((float*)g_xh_part)[p] = 0.f;
}

// ---------------- w_sum ----------------
__global__ void k_wsum(const float* __restrict__ Wd) {
    int row = blockIdx.x;
    __shared__ float red[256];
    float s = 0.f;
    for (int k = threadIdx.x; k < NF; k += 256) s += Wd[(size_t)row * NF + k];
    red[threadIdx.x] = s;
    __syncthreads();
    for (int off = 128; off; off >>= 1) {
        if (threadIdx.x < off) red[threadIdx.x] += red[threadIdx.x + off];
        __syncthreads();
    }
    if (threadIdx.x == 0) g_wsum[row] = red[0];
}

// ---------------- V2 = [hi(V) | lo(V)] time-major (row = t*BATCH + b) ----------------
__global__ void k_convV(const float* __restrict__ V) {
    int r = blockIdx.x;              // source row b*T_SEQ + t
    int b = r / T_SEQ, t = r % T_SEQ;
    const float4* src4 = (const float4*)(V + (size_t)r * NF);  // NF%4==0
    __half* dst = g_V2 + ((size_t)t * BATCH + b) * KV;
    for (int k4 = threadIdx.x; k4 < NF / 4; k4 += 256) {
        float4 v = src4[k4];
        __half h0 = __float2half_rn(v.x), h1 = __float2half_rn(v.y);
        __half h2 = __float2half_rn(v.z), h3 = __float2half_rn(v.w);
        __half l0 = __float2half_rn(v.x - __half2float(h0));
        __half l1 = __float2half_rn(v.y - __half2float(h1));
        __half l2 = __float2half_rn(v.z - __half2float(h2));
        __half l3 = __float2half_rn(v.w - __half2float(h3));
        ((__half2*)dst)[k4 * 2]     = __halves2half2(h0, h1);
        ((__half2*)dst)[k4 * 2 + 1] = __halves2half2(h2, h3);
        ((__half2*)(dst + KVS))[k4 * 2]     = __halves2half2(l0, l1);
        ((__half2*)(dst + KVS))[k4 * 2 + 1] = __halves2half2(l2, l3);
    }
    if (threadIdx.x < KVS - NF) {
        dst[NF + threadIdx.x] = __float2half(0.f);
        dst[KVS + NF + threadIdx.x] = __float2half(0.f);
    }
}

// ---------------- Wc rows permuted (n = j*4+g): [Wih | Wih | Whh | Whh] ----------------
__global__ void k_convWc(const float* __restrict__ Wih, const float* __restrict__ Whh) {
    int n = blockIdx.x;
    int orig = (n & 3) * HID + (n >> 2);
    __half* dst = g_Wc + (size_t)n * KC;
    const float* srcI = Wih + (size_t)orig * (NF + 1);
    const float* srcH = Whh + (size_t)orig * HID;
    for (int k = threadIdx.x; k < KVS; k += 256) {
        __half hv = __float2half_rn((k < NF) ? srcI[k] : 0.f);
        dst[k] = hv; dst[KVS + k] = hv;
    }
    for (int k = threadIdx.x; k < KHS; k += 256) {
        __half hv = __float2half_rn((k < HID) ? srcH[k] : 0.f);
        dst[KV + k] = hv; dst[KV + KHS + k] = hv;
    }
}

// ------- fused per-step kernel: [V|h] GEMM + imputation prologue + LSTM cell -------
__global__ __launch_bounds__(256, 3) void k_gates(
    const float* __restrict__ V, const float* __restrict__ Wih,
    const float* __restrict__ masks, const float* __restrict__ deltas,
    const float* __restrict__ bdec, const float* __restrict__ Wreg,
    const float* __restrict__ breg, const float* __restrict__ bih,
    const float* __restrict__ bhh, float* __restrict__ outImp, int t)
{
    extern __shared__ char smem[];
    uint32_t sbuf = smem_u32(smem);
    float* stage = (float*)smem;
    __shared__ float wvS[64], wmS[64], biasS[64];
    __shared__ float wsumS[16], bdecS[16], wregS[16];
    __shared__ float alphaS[128], mS[128];
    __shared__ float lossW[4][2];
    int tid = threadIdx.x;
    int bn = blockIdx.x, bm = blockIdx.y;
    int par = t & 1;

    // ---- issue first pipeline stages immediately (overlaps everything below) ----
    const __half* Av = g_V2 + ((size_t)t * BATCH + bm * 128) * KV;
    const __half* Ah = g_h2[par] + (size_t)(bm * 128) * KH;
    const __half* Bb = g_Wc + (size_t)(bn * 64) * KC;
    int nChunks = (t > 0) ? NCH_FULL : NCH_T0;
    gemm_preload(Av, Ah, Bb, sbuf, tid);

    if (tid < 64) {
        int np = bn * 64 + tid;
        int orig = (np & 3) * HID + (np >> 2);
        wvS[tid] = Wih[(size_t)orig * (NF + 1) + (NF - 1)];
        wmS[tid] = Wih[(size_t)orig * (NF + 1) + NF];
        biasS[tid] = bih[orig] + bhh[orig];
    }
    if (tid >= 64 && tid < 80) {
        int jl = tid - 64;
        int j = bn * 16 + jl;
        wsumS[jl] = g_wsum[j];
        bdecS[jl] = bdec[j];
        wregS[jl] = Wreg[j];
    }

    // ---- prologue: per-row regression xh, imputation, alpha, deterministic loss ----
    {
        float nloc = 0.f, dloc = 0.f;
        if (tid < 128) {
            int b = bm * 128 + tid;
            float xh = breg[0];
            #pragma unroll
            for (int p = 0; p < NBN; p++) xh += g_xh_part[par][p][b];
            float m  = masks[b * T_SEQ + t];
            float v  = V[((size_t)b * T_SEQ + t) * NF + (NF - 1)];
            float xvar = v * m + (1.f - m) * xh;
            alphaS[tid] = xvar - v;
            mS[tid] = m;
            if (bn == 0) {
                outImp[b * T_SEQ + t] = xvar;
                nloc = fabsf(xvar - xh) * m;
                dloc = m;
            }
        }
        if (bn == 0) {
            #pragma unroll
            for (int off = 16; off; off >>= 1) {
                nloc += __shfl_xor_sync(0xffffffff, nloc, off);
                dloc += __shfl_xor_sync(0xffffffff, dloc, off);
            }
            if (tid < 128 && (tid & 31) == 0) {
                lossW[tid >> 5][0] = nloc;
                lossW[tid >> 5][1] = dloc;
            }
        }
    }
    __syncthreads();
    if (bn == 0 && tid == 0) {
        float n4 = (lossW[0][0] + lossW[1][0]) + (lossW[2][0] + lossW[3][0]);
        float d4 = (lossW[0][1] + lossW[1][1]) + (lossW[2][1] + lossW[3][1]);
        g_loss_part[t][bm][0] = n4;
        g_loss_part[t][bm][1] = d4;
    }

    float acc[2][4][4];
    #pragma unroll
    for (int a = 0; a < 2; a++)
        #pragma unroll
        for (int b = 0; b < 4; b++)
            #pragma unroll
            for (int c = 0; c < 4; c++) acc[a][b][c] = 0.f;

    gemm_run(Av, Ah, Bb, nChunks, sbuf, acc, tid);

    stage_acc(stage, acc, tid);
    __syncthreads();

    __half* h2n = g_h2[1 - par];
    bool more = (t + 1 < T_SEQ);
    float xh_i[8];
    #pragma unroll
    for (int i = 0; i < 8; i++) xh_i[i] = 0.f;

    #pragma unroll
    for (int i = 0; i < 8; i++) {
        int lin = tid + i * 256;       // 128 rows x 16 jl
        int r = lin >> 4, jl = lin & 15;
        int b = bm * 128 + r;
        float alpha = alphaS[r];
        float m = mS[r];
        int c0 = jl * 4;
        float ig = stage[r * 66 + c0 + 0] + biasS[c0 + 0] + alpha * wvS[c0 + 0] + m * wmS[c0 + 0];
        float fg = stage[r * 66 + c0 + 1] + biasS[c0 + 1] + alpha * wvS[c0 + 1] + m * wmS[c0 + 1];
        float gg = stage[r * 66 + c0 + 2] + biasS[c0 + 2] + alpha * wvS[c0 + 2] + m * wmS[c0 + 2];
        float og = stage[r * 66 + c0 + 3] + biasS[c0 + 3] + alpha * wvS[c0 + 3] + m * wmS[c0 + 3];
        float si = fsigmoid(ig);
        float sf = fsigmoid(fg);
        float so = fsigmoid(og);
        float tg = ftanh(gg);
        int j = bn * 16 + jl;
        size_t ci = (size_t)b * HID + j;
        float c = sf * g_c[ci] + si * tg;
        g_c[ci] = c;
        float hnew = so * ftanh(c);

        float contrib = 0.f;
        if (more) {
            float dnx = deltas[b * T_SEQ + t + 1];
            float wdc = fmaf(dnx, wsumS[jl], bdecS[jl]);
            float gamma = __expf(-fmaxf(wdc, 0.f));
            float hv = hnew * gamma;
            __half hi = __float2half_rn(hv);
            __half lo = __float2half_rn(hv - __half2float(hi));
            h2n[(size_t)b * KH + j] = hi;            // hi section [0, 400)
            h2n[(size_t)b * KH + KHS + j] = lo;      // lo section [416, 816)
            contrib = hv * wregS[jl];
        }
        #pragma unroll
        for (int off = 8; off; off >>= 1)
            contrib += __shfl_xor_sync(0xffffffff, contrib, off);
        if ((tid & 15) == 0) xh_i[i] = contrib;
    }

    if (more && (tid & 15) == 0) {
        #pragma unroll
        for (int i = 0; i < 8; i++) {
            int b = bm * 128 + ((tid + i * 256) >> 4);
            g_xh_part[1 - par][bn][b] = xh_i[i];   // (b, bn) owned by this block
        }
    }
}

// ---------------- finalize loss (deterministic fixed-order reduction) ----------------
__global__ void k_final(float* __restrict__ out) {
    __shared__ float perT[T_SEQ];
    int tid = threadIdx.x;
    int t = tid >> 5, lane = tid & 31;
    if (t < T_SEQ) {
        float n = g_loss_part[t][lane][0] + g_loss_part[t][lane + 32][0];
        float d = g_loss_part[t][lane][1] + g_loss_part[t][lane + 32][1];
        #pragma unroll
        for (int off = 16; off; off >>= 1) {
            n += __shfl_xor_sync(0xffffffff, n, off);
            d += __shfl_xor_sync(0xffffffff, d, off);
        }
        if (lane == 0) perT[t] = n / (d + 1e-5f);
    }
    __syncthreads();
    if (tid == 0) {
        float s = 0.f;
        for (int tt = 0; tt < T_SEQ; tt++) s += perT[tt];
        out[0] = s / (float)T_SEQ;
    }
}

extern "C" void kernel_launch(void* const* d_in, const int* in_sizes, int n_in,
                              void* d_out, int out_size)
{
    const float* V      = (const float*)d_in[0];
    const float* masks  = (const float*)d_in[1];
    const float* deltas = (const float*)d_in[2];
    const float* Wdec   = (const float*)d_in[3];
    const float* bdec   = (const float*)d_in[4];
    const float* Wreg   = (const float*)d_in[5];
    const float* breg   = (const float*)d_in[6];
    const float* Wih    = (const float*)d_in[7];
    const float* Whh    = (const float*)d_in[8];
    const float* bih    = (const float*)d_in[9];
    const float* bhh    = (const float*)d_in[10];
    float* out = (float*)d_out;

    cudaFuncSetAttribute(k_gates, cudaFuncAttributeMaxDynamicSharedMemorySize, SMEM_DYN);

    k_init<<<2048, 256>>>();
    k_wsum<<<HID, 256>>>(Wdec);

    k_convV<<<MROWS, 256>>>(V);
    k_convWc<<<NG, 256>>>(Wih, Whh);

    for (int t = 0; t < T_SEQ; t++) {
        dim3 g4(NBN, NBM);         // (25, 64)
        k_gates<<<g4, 256, SMEM_DYN>>>(V, Wih, masks, deltas, bdec, Wreg, breg,
                                       bih, bhh, out + 1, t);
    }
    k_final<<<1, T_SEQ * 32>>>(out);
}

// round 13
// speedup vs baseline: 1.7238x; 1.3261x over previous
#include <cuda_runtime.h>
#include <cuda_fp16.h>
#include <math.h>
#include <stdint.h>

#define T_SEQ 20
#define NF    812
#define HID   400
#define NG    1600            // 4*HID
#define BATCH 8192
#define MROWS (BATCH * T_SEQ) // 163840
#define KV    832             // V: single fp16 section (26*32)
#define KHS   416             // h per-section K (13*32)
#define KH    (2 * KHS)       // 832: h2 row [hi | lo]
#define KC    (KV + KH)       // 1664 combined K
#define NCH_FULL (KC / 32)    // 52
#define NCH_T0   (KV / 32)    // 26 (h == 0 at t=0)
#define NBN   (NG / 64)       // 25 n-tiles
#define NBM   (BATCH / 128)   // 64 m-tiles

// ---------------- device scratch ----------------
__device__ __half g_V2[(size_t)MROWS * KV];          // ~273 MB, TIME-MAJOR rows (t*BATCH + b)
__device__ __half g_Wc[(size_t)NG * KC];             // ~5.3 MB combined [Wih | Whh | Whh] perm rows
__device__ __half g_h2[2][(size_t)BATCH * KH];       // [hi|lo] decayed h (dbl buf)
__device__ float g_c [BATCH * HID];
__device__ float g_xh_part[2][NBN][BATCH];           // per-bn regression partials (dbl buf)
__device__ float g_loss_part[T_SEQ][NBM][2];         // deterministic loss partials
__device__ float g_wsum[HID];

// ---------------- fast math (MUFU-based; rel err ~1e-7) ----------
__device__ __forceinline__ float fsigmoid(float x) {
    return __fdividef(1.f, 1.f + __expf(-x));
}
__device__ __forceinline__ float ftanh(float x) {
    return 1.f - __fdividef(2.f, 1.f + __expf(2.f * x));
}

// ---------------- PTX helpers ----------------
__device__ __forceinline__ uint32_t smem_u32(const void* p) {
    uint32_t a;
    asm("{ .reg .u64 t; cvta.to.shared.u64 t, %1; cvt.u32.u64 %0, t; }" : "=r"(a) : "l"(p));
    return a;
}
__device__ __forceinline__ void cp_async16(uint32_t saddr, const void* gaddr) {
    asm volatile("cp.async.cg.shared.global [%0], [%1], 16;\n" :: "r"(saddr), "l"(gaddr) : "memory");
}
__device__ __forceinline__ void ldsm_x4(uint32_t* r, uint32_t addr) {
    asm volatile("ldmatrix.sync.aligned.m8n8.x4.shared.b16 {%0,%1,%2,%3}, [%4];"
                 : "=r"(r[0]), "=r"(r[1]), "=r"(r[2]), "=r"(r[3]) : "r"(addr));
}
__device__ __forceinline__ void mma16816(float* d, const uint32_t* a, const uint32_t* b) {
    asm volatile(
        "mma.sync.aligned.m16n8k16.row.col.f32.f16.f16.f32 "
        "{%0,%1,%2,%3}, {%4,%5,%6,%7}, {%8,%9}, {%0,%1,%2,%3};"
        : "+f"(d[0]), "+f"(d[1]), "+f"(d[2]), "+f"(d[3])
        : "r"(a[0]), "r"(a[1]), "r"(a[2]), "r"(a[3]), "r"(b[0]), "r"(b[1]));
}

// A gmem address for tile row + combined-k offset (V section or h sections)
__device__ __forceinline__ const __half* a_addr(const __half* Av, const __half* Ah,
                                                int row, int koff) {
    return (koff < KV) ? (Av + (size_t)row * KV + koff)
                       : (Ah + (size_t)row * KH + (koff - KV));
}

// smem: A 128 rows x 32 halves (80B stride), B 64 rows x 32 halves
#define A_STRIDE_B 80
#define A_TILE_B   (128 * A_STRIDE_B)    // 10240
#define B_TILE_B   (64 * A_STRIDE_B)     // 5120
#define BUF_B      (A_TILE_B + B_TILE_B) // 15360 per stage
#define NSTAGE     4
#define SMEM_DYN   (NSTAGE * BUF_B)      // 61440; epilogue stage 33792 fits

// ------- preload first 3 chunks (issued BEFORE the prologue to overlap latency) -------
__device__ __forceinline__ void gemm_preload(
    const __half* Av, const __half* Ah, const __half* Bbase,
    uint32_t sbuf, int tid)
{
    int lrow = tid >> 2, lseg = tid & 3;
    #pragma unroll
    for (int pc = 0; pc < 3; pc++) {
        uint32_t dst = sbuf + pc * BUF_B;
        int koff = pc * 32 + lseg * 8;
        cp_async16(dst + lrow * A_STRIDE_B + lseg * 16, a_addr(Av, Ah, lrow, koff));
        cp_async16(dst + (lrow + 64) * A_STRIDE_B + lseg * 16, a_addr(Av, Ah, lrow + 64, koff));
        cp_async16(dst + A_TILE_B + lrow * A_STRIDE_B + lseg * 16,
                   Bbase + (size_t)lrow * KC + pc * 32 + lseg * 8);
        asm volatile("cp.async.commit_group;\n" ::: "memory");
    }
}

// ------- mma mainloop body (BM=128, BN=64, BK=32, 8 warps 4x2, 4-stage) -------
__device__ __forceinline__ void gemm_run(
    const __half* Av, const __half* Ah, const __half* Bbase,
    int nChunks, uint32_t sbuf, float acc[2][4][4], int tid)
{
    int lane = tid & 31, w = tid >> 5;
    int wm = w & 3, wn = w >> 2;
    uint32_t aOffBase = (uint32_t)((wm * 32 + (lane & 15)) * A_STRIDE_B + ((lane >> 4) << 4));
    uint32_t bOffBase = (uint32_t)(A_TILE_B +
        (wn * 32 + ((lane >> 4) << 3) + (lane & 7)) * A_STRIDE_B + (((lane >> 3) & 1) << 4));

    int lrow = tid >> 2, lseg = tid & 3;

    for (int c = 0; c < nChunks; c++) {
        if (c + 3 <= nChunks) {
            asm volatile("cp.async.wait_group 2;\n" ::: "memory");
        } else if (c + 2 == nChunks) {
            asm volatile("cp.async.wait_group 1;\n" ::: "memory");
        } else {
            asm volatile("cp.async.wait_group 0;\n" ::: "memory");
        }
        __syncthreads();

        if (c + 3 < nChunks) {
            uint32_t dst = sbuf + ((c + 3) & 3) * BUF_B;
            int koff = (c + 3) * 32 + lseg * 8;
            cp_async16(dst + lrow * A_STRIDE_B + lseg * 16, a_addr(Av, Ah, lrow, koff));
            cp_async16(dst + (lrow + 64) * A_STRIDE_B + lseg * 16, a_addr(Av, Ah, lrow + 64, koff));
            cp_async16(dst + A_TILE_B + lrow * A_STRIDE_B + lseg * 16,
                       Bbase + (size_t)lrow * KC + (c + 3) * 32 + lseg * 8);
            asm volatile("cp.async.commit_group;\n" ::: "memory");
        }

        uint32_t cur = sbuf + (c & 3) * BUF_B;
        #pragma unroll
        for (int kc = 0; kc < 2; kc++) {
            uint32_t aregs[2][4], bregs[2][4];
            ldsm_x4(aregs[0], cur + aOffBase + kc * 32);
            ldsm_x4(aregs[1], cur + aOffBase + 16 * A_STRIDE_B + kc * 32);
            ldsm_x4(bregs[0], cur + bOffBase + kc * 32);
            ldsm_x4(bregs[1], cur + bOffBase + 16 * A_STRIDE_B + kc * 32);
            #pragma unroll
            for (int mi = 0; mi < 2; mi++)
                #pragma unroll
                for (int ni = 0; ni < 4; ni++)
                    mma16816(acc[mi][ni], aregs[mi], &bregs[ni >> 1][(ni & 1) * 2]);
        }
    }
    __syncthreads();  // protect smem before epilogue staging reuses it
}

// stage acc -> smem fp32 [128][66]
__device__ __forceinline__ void stage_acc(float* stage, float acc[2][4][4], int tid) {
    int lane = tid & 31, w = tid >> 5;
    int wm = w & 3, wn = w >> 2;
    #pragma unroll
    for (int mi = 0; mi < 2; mi++)
        #pragma unroll
        for (int ni = 0; ni < 4; ni++) {
            int r0 = wm * 32 + mi * 16 + (lane >> 2);
            int cc = wn * 32 + ni * 8 + (lane & 3) * 2;
            *(float2*)&stage[r0 * 66 + cc]       = make_float2(acc[mi][ni][0], acc[mi][ni][1]);
            *(float2*)&stage[(r0 + 8) * 66 + cc] = make_float2(acc[mi][ni][2], acc[mi][ni][3]);
        }
}

// ---------------- init ----------------
__global__ void k_init() {
    long i = (long)blockIdx.x * blockDim.x + threadIdx.x;
    long stride = (long)gridDim.x * blockDim.x;
    for (long p = i; p < (long)BATCH * HID; p += stride) g_c[p] = 0.f;
    for (long p = i; p < 2L * BATCH * KH; p += stride) ((__half*)g_h2)[p] = __float2half(0.f);
    for (long p = i; p < 2L * NBN * BATCH; p += stride) ((float*)g_xh_part)[p] = 0.f;
}

// ---------------- w_sum ----------------
__global__ void k_wsum(const float* __restrict__ Wd) {
    int row = blockIdx.x;
    __shared__ float red[256];
    float s = 0.f;
    for (int k = threadIdx.x; k < NF; k += 256) s += Wd[(size_t)row * NF + k];
    red[threadIdx.x] = s;
    __syncthreads();
    for (int off = 128; off; off >>= 1) {
        if (threadIdx.x < off) red[threadIdx.x] += red[threadIdx.x + off];
        __syncthreads();
    }
    if (threadIdx.x == 0) g_wsum[row] = red[0];
}

// ---------------- V2 = fp16(V) time-major (row = t*BATCH + b) ----------------
__global__ void k_convV(const float* __restrict__ V) {
    int r = blockIdx.x;              // source row b*T_SEQ + t
    int b = r / T_SEQ, t = r % T_SEQ;
    const float4* src4 = (const float4*)(V + (size_t)r * NF);  // NF%4==0
    __half* dst = g_V2 + ((size_t)t * BATCH + b) * KV;
    for (int k4 = threadIdx.x; k4 < NF / 4; k4 += 256) {
        float4 v = src4[k4];
        __half h0 = __float2half_rn(v.x), h1 = __float2half_rn(v.y);
        __half h2 = __float2half_rn(v.z), h3 = __float2half_rn(v.w);
        ((__half2*)dst)[k4 * 2]     = __halves2half2(h0, h1);
        ((__half2*)dst)[k4 * 2 + 1] = __halves2half2(h2, h3);
    }
    if (threadIdx.x < KV - NF) dst[NF + threadIdx.x] = __float2half(0.f);
}

// ------- Wc rows permuted (n = j*4+g): [Wih(832) | Whh(416) | Whh(416)] -------
__global__ void k_convWc(const float* __restrict__ Wih, const float* __restrict__ Whh) {
    int n = blockIdx.x;
    int orig = (n & 3) * HID + (n >> 2);
    __half* dst = g_Wc + (size_t)n * KC;
    const float* srcI = Wih + (size_t)orig * (NF + 1);
    const float* srcH = Whh + (size_t)orig * HID;
    for (int k = threadIdx.x; k < KV; k += 256)
        dst[k] = __float2half_rn((k < NF) ? srcI[k] : 0.f);
    for (int k = threadIdx.x; k < KHS; k += 256) {
        __half hv = __float2half_rn((k < HID) ? srcH[k] : 0.f);
        dst[KV + k] = hv; dst[KV + KHS + k] = hv;
    }
}

// ------- fused per-step kernel: [V|h] GEMM + imputation prologue + LSTM cell -------
__global__ __launch_bounds__(256, 3) void k_gates(
    const float* __restrict__ V, const float* __restrict__ Wih,
    const float* __restrict__ masks, const float* __restrict__ deltas,
    const float* __restrict__ bdec, const float* __restrict__ Wreg,
    const float* __restrict__ breg, const float* __restrict__ bih,
    const float* __restrict__ bhh, float* __restrict__ outImp, int t)
{
    extern __shared__ char smem[];
    uint32_t sbuf = smem_u32(smem);
    float* stage = (float*)smem;
    __shared__ float wvS[64], wmS[64], biasS[64];
    __shared__ float wsumS[16], bdecS[16], wregS[16];
    __shared__ float alphaS[128], mS[128];
    __shared__ float lossW[4][2];
    int tid = threadIdx.x;
    int bn = blockIdx.x, bm = blockIdx.y;
    int par = t & 1;

    // ---- issue first pipeline stages immediately (overlaps everything below) ----
    const __half* Av = g_V2 + ((size_t)t * BATCH + bm * 128) * KV;
    const __half* Ah = g_h2[par] + (size_t)(bm * 128) * KH;
    const __half* Bb = g_Wc + (size_t)(bn * 64) * KC;
    int nChunks = (t > 0) ? NCH_FULL : NCH_T0;
    gemm_preload(Av, Ah, Bb, sbuf, tid);

    if (tid < 64) {
        int np = bn * 64 + tid;
        int orig = (np & 3) * HID + (np >> 2);
        wvS[tid] = Wih[(size_t)orig * (NF + 1) + (NF - 1)];
        wmS[tid] = Wih[(size_t)orig * (NF + 1) + NF];
        biasS[tid] = bih[orig] + bhh[orig];
    }
    if (tid >= 64 && tid < 80) {
        int jl = tid - 64;
        int j = bn * 16 + jl;
        wsumS[jl] = g_wsum[j];
        bdecS[jl] = bdec[j];
        wregS[jl] = Wreg[j];
    }

    // ---- prologue: per-row regression xh, imputation, alpha, deterministic loss ----
    {
        float nloc = 0.f, dloc = 0.f;
        if (tid < 128) {
            int b = bm * 128 + tid;
            float xh = breg[0];
            #pragma unroll
            for (int p = 0; p < NBN; p++) xh += g_xh_part[par][p][b];
            float m  = masks[b * T_SEQ + t];
            float v  = V[((size_t)b * T_SEQ + t) * NF + (NF - 1)];
            float xvar = v * m + (1.f - m) * xh;
            alphaS[tid] = xvar - v;
            mS[tid] = m;
            if (bn == 0) {
                outImp[b * T_SEQ + t] = xvar;
                nloc = fabsf(xvar - xh) * m;
                dloc = m;
            }
        }
        if (bn == 0) {
            #pragma unroll
            for (int off = 16; off; off >>= 1) {
                nloc += __shfl_xor_sync(0xffffffff, nloc, off);
                dloc += __shfl_xor_sync(0xffffffff, dloc, off);
            }
            if (tid < 128 && (tid & 31) == 0) {
                lossW[tid >> 5][0] = nloc;
                lossW[tid >> 5][1] = dloc;
            }
        }
    }
    __syncthreads();
    if (bn == 0 && tid == 0) {
        float n4 = (lossW[0][0] + lossW[1][0]) + (lossW[2][0] + lossW[3][0]);
        float d4 = (lossW[0][1] + lossW[1][1]) + (lossW[2][1] + lossW[3][1]);
        g_loss_part[t][bm][0] = n4;
        g_loss_part[t][bm][1] = d4;
    }

    float acc[2][4][4];
    #pragma unroll
    for (int a = 0; a < 2; a++)
        #pragma unroll
        for (int b = 0; b < 4; b++)
            #pragma unroll
            for (int c = 0; c < 4; c++) acc[a][b][c] = 0.f;

    gemm_run(Av, Ah, Bb, nChunks, sbuf, acc, tid);

    stage_acc(stage, acc, tid);
    __syncthreads();

    __half* h2n = g_h2[1 - par];
    bool more = (t + 1 < T_SEQ);
    float xh_i[8];
    #pragma unroll
    for (int i = 0; i < 8; i++) xh_i[i] = 0.f;

    #pragma unroll
    for (int i = 0; i < 8; i++) {
        int lin = tid + i * 256;       // 128 rows x 16 jl
        int r = lin >> 4, jl = lin & 15;
        int b = bm * 128 + r;
        float alpha = alphaS[r];
        float m = mS[r];
        int c0 = jl * 4;
        float ig = stage[r * 66 + c0 + 0] + biasS[c0 + 0] + alpha * wvS[c0 + 0] + m * wmS[c0 + 0];
        float fg = stage[r * 66 + c0 + 1] + biasS[c0 + 1] + alpha * wvS[c0 + 1] + m * wmS[c0 + 1];
        float gg = stage[r * 66 + c0 + 2] + biasS[c0 + 2] + alpha * wvS[c0 + 2] + m * wmS[c0 + 2];
        float og = stage[r * 66 + c0 + 3] + biasS[c0 + 3] + alpha * wvS[c0 + 3] + m * wmS[c0 + 3];
        float si = fsigmoid(ig);
        float sf = fsigmoid(fg);
        float so = fsigmoid(og);
        float tg = ftanh(gg);
        int j = bn * 16 + jl;
        size_t ci = (size_t)b * HID + j;
        float c = sf * g_c[ci] + si * tg;
        g_c[ci] = c;
        float hnew = so * ftanh(c);

        float contrib = 0.f;
        if (more) {
            float dnx = deltas[b * T_SEQ + t + 1];
            float wdc = fmaf(dnx, wsumS[jl], bdecS[jl]);
            float gamma = __expf(-fmaxf(wdc, 0.f));
            float hv = hnew * gamma;
            __half hi = __float2half_rn(hv);
            __half lo = __float2half_rn(hv - __half2float(hi));
            h2n[(size_t)b * KH + j] = hi;            // hi section [0, 400)
            h2n[(size_t)b * KH + KHS + j] = lo;      // lo section [416, 816)
            contrib = hv * wregS[jl];
        }
        #pragma unroll
        for (int off = 8; off; off >>= 1)
            contrib += __shfl_xor_sync(0xffffffff, contrib, off);
        if ((tid & 15) == 0) xh_i[i] = contrib;
    }

    if (more && (tid & 15) == 0) {
        #pragma unroll
        for (int i = 0; i < 8; i++) {
            int b = bm * 128 + ((tid + i * 256) >> 4);
            g_xh_part[1 - par][bn][b] = xh_i[i];   // (b, bn) owned by this block
        }
    }
}

// ---------------- finalize loss (deterministic fixed-order reduction) ----------------
__global__ void k_final(float* __restrict__ out) {
    __shared__ float perT[T_SEQ];
    int tid = threadIdx.x;
    int t = tid >> 5, lane = tid & 31;
    if (t < T_SEQ) {
        float n = g_loss_part[t][lane][0] + g_loss_part[t][lane + 32][0];
        float d = g_loss_part[t][lane][1] + g_loss_part[t][lane + 32][1];
        #pragma unroll
        for (int off = 16; off; off >>= 1) {
            n += __shfl_xor_sync(0xffffffff, n, off);
            d += __shfl_xor_sync(0xffffffff, d, off);
        }
        if (lane == 0) perT[t] = n / (d + 1e-5f);
    }
    __syncthreads();
    if (tid == 0) {
        float s = 0.f;
        for (int tt = 0; tt < T_SEQ; tt++) s += perT[tt];
        out[0] = s / (float)T_SEQ;
    }
}

extern "C" void kernel_launch(void* const* d_in, const int* in_sizes, int n_in,
                              void* d_out, int out_size)
{
    const float* V      = (const float*)d_in[0];
    const float* masks  = (const float*)d_in[1];
    const float* deltas = (const float*)d_in[2];
    const float* Wdec   = (const float*)d_in[3];
    const float* bdec   = (const float*)d_in[4];
    const float* Wreg   = (const float*)d_in[5];
    const float* breg   = (const float*)d_in[6];
    const float* Wih    = (const float*)d_in[7];
    const float* Whh    = (const float*)d_in[8];
    const float* bih    = (const float*)d_in[9];
    const float* bhh    = (const float*)d_in[10];
    float* out = (float*)d_out;

    cudaFuncSetAttribute(k_gates, cudaFuncAttributeMaxDynamicSharedMemorySize, SMEM_DYN);

    k_init<<<2048, 256>>>();
    k_wsum<<<HID, 256>>>(Wdec);

    k_convV<<<MROWS, 256>>>(V);
    k_convWc<<<NG, 256>>>(Wih, Whh);

    for (int t = 0; t < T_SEQ; t++) {
        dim3 g4(NBN, NBM);         // (25, 64)
        k_gates<<<g4, 256, SMEM_DYN>>>(V, Wih, masks, deltas, bdec, Wreg, breg,
                                       bih, bhh, out + 1, t);
    }
    k_final<<<1, T_SEQ * 32>>>(out);
}